// round 11
// baseline (speedup 1.0000x reference)
#include <cuda_runtime.h>
#include <cuda_bf16.h>
#include <cstdint>
#include <math.h>

#define U_  256
#define B_  32
#define T_  2048
#define X3  768      // 3U
#define YCH 512      // 2U
#define KP  260      // padded k-stride
#define CL  8        // cluster size (ranks)
#define CPR 32       // columns per rank
#define BGR 4        // batch rows per cluster
#define REC_THREADS 512
// smem floats: mbar pad(4) + W(96*KP) + H(2*BGR*KP) + Red(3*128*4)
#define SM_W    4
#define SM_H    (SM_W + 3*CPR*KP)
#define SM_RED  (SM_H + 2*BGR*KP)
#define REC_SMEM_FLOATS (SM_RED + 3*128*4)
#define REC_SMEM_BYTES  (REC_SMEM_FLOATS*4)

// GEMM dynamic smem: 4 arrays x 2 stages x 128x40 halves
#define G_STG   5120                    // halves per array-stage
#define GEMM_SMEM_BYTES (8*G_STG*2)     // 81920 B

// Scratch: input projections per direction + inter-layer hidden states
__device__ float g_xp[2][B_*T_*X3];   // [dir][(b*T+t)*768 + c]
__device__ float g_h[2][B_][U_];      // final hidden state handoff between layers

// ---------------------------------------------------------------------------
// helpers
// ---------------------------------------------------------------------------
__device__ __forceinline__ uint32_t smem_u32(const void* p) {
    uint32_t a;
    asm("{ .reg .u64 t; cvta.to.shared.u64 t, %1; cvt.u32.u64 %0, t; }"
        : "=r"(a) : "l"(p));
    return a;
}
__device__ __forceinline__ uint32_t mapa_rank(uint32_t addr, int r) {
    uint32_t out;
    asm("mapa.shared::cluster.u32 %0, %1, %2;" : "=r"(out) : "r"(addr), "r"(r));
    return out;
}
__device__ __forceinline__ void st_cluster_f32(uint32_t addr, float v) {
    asm volatile("st.shared::cluster.f32 [%0], %1;" :: "r"(addr), "f"(v));
}
__device__ __forceinline__ uint32_t ctarank() {
    uint32_t r; asm("mov.u32 %0, %%cluster_ctarank;" : "=r"(r)); return r;
}
#define CLUSTER_ARRIVE_() asm volatile("barrier.cluster.arrive.aligned;" ::: "memory")
#define CLUSTER_WAIT_()   asm volatile("barrier.cluster.wait.aligned;"   ::: "memory")

__device__ __forceinline__ void mbar_init(uint32_t addr, uint32_t cnt) {
    asm volatile("mbarrier.init.shared.b64 [%0], %1;" :: "r"(addr), "r"(cnt) : "memory");
}
__device__ __forceinline__ void mbar_arrive_cluster(uint32_t addr) {
    asm volatile("mbarrier.arrive.release.cluster.shared::cluster.b64 _, [%0];"
                 :: "r"(addr) : "memory");
}
__device__ __forceinline__ void mbar_wait_parity(uint32_t addr, uint32_t parity) {
    asm volatile(
        "{\n\t"
        ".reg .pred P;\n\t"
        "WL%=:\n\t"
        "mbarrier.try_wait.parity.acquire.cluster.shared::cta.b64 P, [%0], %1, 0x989680;\n\t"
        "@!P bra WL%=;\n\t"
        "}"
        :: "r"(addr), "r"(parity) : "memory");
}

__device__ __forceinline__ float fast_sigmoid(float x) {
    return __fdividef(1.f, 1.f + __expf(-x));
}
__device__ __forceinline__ float fast_tanh(float x) {
    float e = __expf(-2.f * x);
    return __fdividef(1.f - e, 1.f + e);
}

// Packed dual fp32 FMA (Blackwell family, PTX ISA 8.6, sm_100+)
__device__ __forceinline__ void ffma2(unsigned long long& d,
                                      unsigned long long a,
                                      unsigned long long b) {
    asm("fma.rn.f32x2 %0, %1, %2, %0;" : "+l"(d) : "l"(a), "l"(b));
}
__device__ __forceinline__ float upk_sum(unsigned long long v) {
    float lo, hi;
    asm("mov.b64 {%0, %1}, %2;" : "=f"(lo), "=f"(hi) : "l"(v));
    return lo + hi;
}

// bf16 HMMA m16n8k16, fp32 accumulate (baseline PTX, legal on sm_100)
__device__ __forceinline__ void mma16816(float* c,
    uint32_t a0, uint32_t a1, uint32_t a2, uint32_t a3,
    uint32_t b0, uint32_t b1)
{
    asm volatile(
        "mma.sync.aligned.m16n8k16.row.col.f32.bf16.bf16.f32 "
        "{%0,%1,%2,%3}, {%4,%5,%6,%7}, {%8,%9}, {%0,%1,%2,%3};"
        : "+f"(c[0]), "+f"(c[1]), "+f"(c[2]), "+f"(c[3])
        : "r"(a0), "r"(a1), "r"(a2), "r"(a3), "r"(b0), "r"(b1));
}

// ---------------------------------------------------------------------------
// Layer 0 input projection: xp = x * Wk[0,:] + b[0,:]  (in_dim = 1)
// ---------------------------------------------------------------------------
__global__ void layer0_xp_kernel(const float* __restrict__ x,
                                 const float* __restrict__ fwk,
                                 const float* __restrict__ fwb,
                                 const float* __restrict__ bwk,
                                 const float* __restrict__ bwb)
{
    int i4 = blockIdx.x * blockDim.x + threadIdx.x;
    const int tot4 = B_*T_*X3/4;
    if (i4 >= tot4) return;
    int e  = i4 * 4;
    int c  = e % X3;
    int bt = e / X3;
    float xv = __ldg(&x[bt]);
    float4 kf = *(const float4*)&fwk[c];
    float4 bf = *(const float4*)&fwb[c];
    float4 kb = *(const float4*)&bwk[c];
    float4 bb = *(const float4*)&bwb[c];
    float4 of, ob;
    of.x = xv*kf.x + bf.x; of.y = xv*kf.y + bf.y;
    of.z = xv*kf.z + bf.z; of.w = xv*kf.w + bf.w;
    ob.x = xv*kb.x + bb.x; ob.y = xv*kb.y + bb.y;
    ob.z = xv*kb.z + bb.z; ob.w = xv*kb.w + bb.w;
    *(float4*)&g_xp[0][e] = of;
    *(float4*)&g_xp[1][e] = ob;
}

// ---------------------------------------------------------------------------
// Layers 1/2 input projection via bf16-split HMMA GEMM. (R9/R10 DB version)
// ---------------------------------------------------------------------------
__global__ void __launch_bounds__(256) gemm_xp_mma_kernel(
    const float* __restrict__ Yin,
    const float* __restrict__ kfw, const float* __restrict__ bfw,
    const float* __restrict__ kbw, const float* __restrict__ bbw)
{
    extern __shared__ __nv_bfloat16 gsm[];

    int dir = blockIdx.z;
    const float* Wk   = dir ? kbw : kfw;
    const float* bias = dir ? bbw : bfw;   // row 0 = input bias
    float* out = g_xp[dir];

    int n0 = blockIdx.x * 128;
    int m0 = blockIdx.y * 128;

    int tid  = threadIdx.x;
    int lane = tid & 31, wid = tid >> 5;
    int wm = wid >> 2, wn = wid & 3;       // warp tile: rows wm*64, cols wn*32
    int gr = lane >> 2, tc = (lane & 3) * 2;

    int arow0 = tid >> 5;      // + 8j
    int ak    = tid & 31;
    int bk0   = tid >> 7;      // + 2j
    int bn    = tid & 127;

    float ra[16], rb[16];

    float acc[4][4][4];
#pragma unroll
    for (int i = 0; i < 4; i++)
#pragma unroll
        for (int j = 0; j < 4; j++)
#pragma unroll
            for (int q = 0; q < 4; q++) acc[i][j][q] = 0.f;

    // ---- stage kt=0 ----
    {
#pragma unroll
        for (int j = 0; j < 16; j++)
            ra[j] = __ldg(&Yin[(size_t)(m0 + arow0 + 8*j)*YCH + ak]);
#pragma unroll
        for (int j = 0; j < 16; j++)
            rb[j] = __ldg(&Wk[(size_t)(bk0 + 2*j)*X3 + n0 + bn]);
        __nv_bfloat16* pAh = gsm;
        __nv_bfloat16* pAl = gsm + 2*G_STG;
        __nv_bfloat16* pBh = gsm + 4*G_STG;
        __nv_bfloat16* pBl = gsm + 6*G_STG;
#pragma unroll
        for (int j = 0; j < 16; j++) {
            float v = ra[j];
            __nv_bfloat16 hi = __float2bfloat16(v);
            pAh[(arow0 + 8*j)*40 + ak] = hi;
            pAl[(arow0 + 8*j)*40 + ak] = __float2bfloat16(v - __bfloat162float(hi));
        }
#pragma unroll
        for (int j = 0; j < 16; j++) {
            float v = rb[j];
            __nv_bfloat16 hi = __float2bfloat16(v);
            pBh[bn*40 + bk0 + 2*j] = hi;
            pBl[bn*40 + bk0 + 2*j] = __float2bfloat16(v - __bfloat162float(hi));
        }
    }
    __syncthreads();

    for (int kt = 0; kt < 16; kt++) {
        int cur = kt & 1;
        if (kt < 15) {
            int kc = (kt + 1) * 32;
#pragma unroll
            for (int j = 0; j < 16; j++)
                ra[j] = __ldg(&Yin[(size_t)(m0 + arow0 + 8*j)*YCH + kc + ak]);
#pragma unroll
            for (int j = 0; j < 16; j++)
                rb[j] = __ldg(&Wk[(size_t)(kc + bk0 + 2*j)*X3 + n0 + bn]);
        }

        const __nv_bfloat16* pAh = gsm +            cur*G_STG;
        const __nv_bfloat16* pAl = gsm + 2*G_STG +  cur*G_STG;
        const __nv_bfloat16* pBh = gsm + 4*G_STG +  cur*G_STG;
        const __nv_bfloat16* pBl = gsm + 6*G_STG +  cur*G_STG;

#pragma unroll
        for (int kk = 0; kk < 32; kk += 16) {
            uint32_t fbh[4][2], fbl[4][2];
#pragma unroll
            for (int nf = 0; nf < 4; nf++) {
                int n = wn*32 + nf*8 + gr;
                fbh[nf][0] = *(const uint32_t*)&pBh[n*40 + kk + tc];
                fbh[nf][1] = *(const uint32_t*)&pBh[n*40 + kk + tc + 8];
                fbl[nf][0] = *(const uint32_t*)&pBl[n*40 + kk + tc];
                fbl[nf][1] = *(const uint32_t*)&pBl[n*40 + kk + tc + 8];
            }
            uint32_t fah[4][4], fal[4][4];
#pragma unroll
            for (int mf = 0; mf < 4; mf++) {
                int r = wm*64 + mf*16 + gr;
                fah[mf][0] = *(const uint32_t*)&pAh[(r    )*40 + kk + tc];
                fah[mf][1] = *(const uint32_t*)&pAh[(r + 8)*40 + kk + tc];
                fah[mf][2] = *(const uint32_t*)&pAh[(r    )*40 + kk + tc + 8];
                fah[mf][3] = *(const uint32_t*)&pAh[(r + 8)*40 + kk + tc + 8];
                fal[mf][0] = *(const uint32_t*)&pAl[(r    )*40 + kk + tc];
                fal[mf][1] = *(const uint32_t*)&pAl[(r + 8)*40 + kk + tc];
                fal[mf][2] = *(const uint32_t*)&pAl[(r    )*40 + kk + tc + 8];
                fal[mf][3] = *(const uint32_t*)&pAl[(r + 8)*40 + kk + tc + 8];
            }
#pragma unroll
            for (int mf = 0; mf < 4; mf++)
#pragma unroll
                for (int nf = 0; nf < 4; nf++)
                    mma16816(acc[mf][nf], fah[mf][0], fah[mf][1], fah[mf][2],
                             fah[mf][3], fbh[nf][0], fbh[nf][1]);
#pragma unroll
            for (int mf = 0; mf < 4; mf++)
#pragma unroll
                for (int nf = 0; nf < 4; nf++)
                    mma16816(acc[mf][nf], fal[mf][0], fal[mf][1], fal[mf][2],
                             fal[mf][3], fbh[nf][0], fbh[nf][1]);
#pragma unroll
            for (int mf = 0; mf < 4; mf++)
#pragma unroll
                for (int nf = 0; nf < 4; nf++)
                    mma16816(acc[mf][nf], fah[mf][0], fah[mf][1], fah[mf][2],
                             fah[mf][3], fbl[nf][0], fbl[nf][1]);
        }

        if (kt < 15) {
            int nxt = cur ^ 1;
            __nv_bfloat16* qAh = gsm +            nxt*G_STG;
            __nv_bfloat16* qAl = gsm + 2*G_STG +  nxt*G_STG;
            __nv_bfloat16* qBh = gsm + 4*G_STG +  nxt*G_STG;
            __nv_bfloat16* qBl = gsm + 6*G_STG +  nxt*G_STG;
#pragma unroll
            for (int j = 0; j < 16; j++) {
                float v = ra[j];
                __nv_bfloat16 hi = __float2bfloat16(v);
                qAh[(arow0 + 8*j)*40 + ak] = hi;
                qAl[(arow0 + 8*j)*40 + ak] = __float2bfloat16(v - __bfloat162float(hi));
            }
#pragma unroll
            for (int j = 0; j < 16; j++) {
                float v = rb[j];
                __nv_bfloat16 hi = __float2bfloat16(v);
                qBh[bn*40 + bk0 + 2*j] = hi;
                qBl[bn*40 + bk0 + 2*j] = __float2bfloat16(v - __bfloat162float(hi));
            }
        }
        __syncthreads();
    }

    // Epilogue
#pragma unroll
    for (int mf = 0; mf < 4; mf++) {
        int row = m0 + wm*64 + mf*16 + gr;
#pragma unroll
        for (int nf = 0; nf < 4; nf++) {
            int col = n0 + wn*32 + nf*8 + tc;
            float b0 = __ldg(&bias[col]), b1 = __ldg(&bias[col + 1]);
            float2 lo, hi;
            lo.x = acc[mf][nf][0] + b0; lo.y = acc[mf][nf][1] + b1;
            hi.x = acc[mf][nf][2] + b0; hi.y = acc[mf][nf][3] + b1;
            *(float2*)&out[(size_t)row * X3 + col]       = lo;
            *(float2*)&out[(size_t)(row + 8) * X3 + col] = hi;
        }
    }
}

// ---------------------------------------------------------------------------
// Recurrence. Grid = 128 CTAs, clusters of 8, 512 threads.
//   R11: CL=8 (rank owns 32 cols, 4 batch rows/cluster) — halves per-step
//   smem weight traffic (96 rows x 256 k = ~98KB -> 768-cyc crossbar floor,
//   balancing the 768-cyc FMA floor). Same R8/R10 mbarrier step protocol.
// ---------------------------------------------------------------------------
__global__ void __cluster_dims__(CL, 1, 1) __launch_bounds__(REC_THREADS, 1)
rec_kernel(const float* __restrict__ wr_fw, const float* __restrict__ bias_fw,
           const float* __restrict__ wr_bw, const float* __restrict__ bias_bw,
           float* __restrict__ y, float* __restrict__ hcat, int layer)
{
    extern __shared__ float sm[];
    float* Wsm = sm + SM_W;          // [96][KP]
    float* Hsm = sm + SM_H;          // [2][BGR][KP]
    float* Red = sm + SM_RED;        // [3][128][4]
    uint32_t mbar = smem_u32(sm);    // 8B mbarrier at sm[0..1]

    int rank = (int)ctarank();
    int cidx = blockIdx.x >> 3;       // 0..15
    int dir  = cidx >> 3;             // 0 fw, 1 bw
    int bg   = cidx & 7;              // batch group (4 rows)
    int tid  = threadIdx.x;
    int kh   = tid >> 7;              // k-quarter 0..3
    int tl   = tid & 127;
    int jl   = tl >> 2;               // 0..31 local column
    int bl   = tl & 3;                // 0..3 local batch
    int jglob = rank*CPR + jl;
    int bglob = bg*BGR + bl;

    const float* Wr   = dir ? wr_bw   : wr_fw;
    const float* bias = dir ? bias_bw : bias_fw;
    const float* xp   = g_xp[dir];

    if (tid == 0) mbar_init(mbar, CL);

    // Load weight slice: Wsm[(g*32+j)*KP + k] = Wr[k][g*256 + rank*32 + j]
    for (int idx = tid; idx < 96*256; idx += REC_THREADS) {
        int k   = idx / 96;
        int r96 = idx - k*96;
        int g = r96 >> 5, j = r96 & 31;
        Wsm[(g*CPR + j)*KP + k] = __ldg(&Wr[k*X3 + g*256 + rank*CPR + j]);
    }
    // Initial hidden state into parity-0 buffer
    for (int i = tid; i < BGR*256; i += REC_THREADS) {
        int b = i >> 8, k = i & 255;
        Hsm[b*KP + k] = layer ? g_h[dir][bg*BGR + b][k] : 0.f;
    }
    // Recurrent biases (row 1 of bias array) — only needed by kh=0
    float bz = 0.f, br = 0.f, bh = 0.f;
    if (kh == 0) {
        bz = __ldg(&bias[X3 +       jglob]);
        br = __ldg(&bias[X3 + 256 + jglob]);
        bh = __ldg(&bias[X3 + 512 + jglob]);
    }
    __syncthreads();
    CLUSTER_ARRIVE_();   // all mbarriers initialised + H/W loaded cluster-wide
    CLUSTER_WAIT_();

    uint32_t hbase = smem_u32(Hsm);
    uint32_t peerH[CL], peerM[CL];
#pragma unroll
    for (int r = 0; r < CL; r++) {
        peerH[r] = mapa_rank(hbase, r);
        peerM[r] = mapa_rank(mbar, r);
    }
    uint32_t off_self = (uint32_t)((bl*KP + jglob) * 4);

    // packed-pair views of weight rows (16B = 2 x f32x2 lanes)
    const ulonglong2* wz2 = (const ulonglong2*)(Wsm + (          jl)*KP) + kh*16;
    const ulonglong2* wr2 = (const ulonglong2*)(Wsm + ( CPR    + jl)*KP) + kh*16;
    const ulonglong2* wh2 = (const ulonglong2*)(Wsm + (2*CPR   + jl)*KP) + kh*16;

    // h(t-1) for this (jglob,bl) carried in-register by kh==0 threads
    float hn = (kh == 0) ? Hsm[bl*KP + jglob] : 0.f;

    // prefetch xp for step 0
    float xz = 0.f, xr = 0.f, xh = 0.f;
    if (kh == 0) {
        int tt0 = dir ? (T_-1) : 0;
        size_t xrow = ((size_t)bglob*T_ + tt0) * X3;
        xz = __ldg(&xp[xrow +       jglob]);
        xr = __ldg(&xp[xrow + 256 + jglob]);
        xh = __ldg(&xp[xrow + 512 + jglob]);
    }

    int p = 0;
    for (int s = 0; s < T_; s++) {
        int tt = dir ? (T_-1-s) : s;

        const ulonglong2* hv2 =
            (const ulonglong2*)(Hsm + (p*BGR + bl)*KP) + kh*16;
        unsigned long long az0 = 0ull, az1 = 0ull;
        unsigned long long ar0 = 0ull, ar1 = 0ull;
        unsigned long long ah0 = 0ull, ah1 = 0ull;
#pragma unroll
        for (int k4 = 0; k4 < 16; k4++) {
            ulonglong2 h2 = hv2[k4];
            ulonglong2 w;
            w = wz2[k4]; ffma2(az0, w.x, h2.x); ffma2(az1, w.y, h2.y);
            w = wr2[k4]; ffma2(ar0, w.x, h2.x); ffma2(ar1, w.y, h2.y);
            w = wh2[k4]; ffma2(ah0, w.x, h2.x); ffma2(ah1, w.y, h2.y);
        }
        float pz = upk_sum(az0) + upk_sum(az1);
        float pr = upk_sum(ar0) + upk_sum(ar1);
        float ph = upk_sum(ah0) + upk_sum(ah1);

        if (kh) {
            float4 v; v.x = pz; v.y = pr; v.z = ph; v.w = 0.f;
            *(float4*)&Red[((kh-1)*128 + tl)*4] = v;
        }
        __syncthreads();

        if (!kh) {
            float4 v1 = *(const float4*)&Red[(        tl)*4];
            float4 v2 = *(const float4*)&Red[(128  + tl)*4];
            float4 v3 = *(const float4*)&Red[(256  + tl)*4];
            float hz = pz + v1.x + v2.x + v3.x + bz;
            float hr = pr + v1.y + v2.y + v3.y + br;
            float hh = ph + v1.z + v2.z + v3.z + bh;
            float z    = fast_sigmoid(xz + hz);
            float r    = fast_sigmoid(xr + hr);
            float cand = fast_tanh(xh + r * hh);
            hn = fmaf(z, hn - cand, cand);      // z*h + (1-z)*cand

            // push to next-parity h buffer of every rank (incl. self)
            uint32_t off = off_self + (uint32_t)((p ^ 1) * BGR * KP * 4);
#pragma unroll
            for (int rr = 0; rr < CL; rr++) st_cluster_f32(peerH[rr] + off, hn);
        }

        __syncthreads();                 // all pushes issued CTA-wide
        if (tid < CL) mbar_arrive_cluster(peerM[tid]);

        // latency cover between arrive and wait: y store + next-x prefetch
        if (!kh) {
            y[((size_t)bglob*T_ + tt)*YCH + dir*256 + jglob] = hn;
            if (s + 1 < T_) {
                int tn = dir ? (T_-2-s) : (s+1);
                size_t xrow = ((size_t)bglob*T_ + tn) * X3;
                xz = __ldg(&xp[xrow +       jglob]);
                xr = __ldg(&xp[xrow + 256 + jglob]);
                xh = __ldg(&xp[xrow + 512 + jglob]);
            }
        }

        mbar_wait_parity(mbar, (uint32_t)(s & 1));
        p ^= 1;
    }

    if (kh == 0) {
        if (layer == 2)
            hcat[(size_t)bglob*YCH + dir*256 + jglob] = hn;
        else
            g_h[dir][bglob][jglob] = hn;
    }
    CLUSTER_ARRIVE_();   // keep smem alive until all peers' final pushes land
    CLUSTER_WAIT_();
}

// ---------------------------------------------------------------------------
// launch
// ---------------------------------------------------------------------------
extern "C" void kernel_launch(void* const* d_in, const int* in_sizes, int n_in,
                              void* d_out, int out_size)
{
    (void)in_sizes; (void)n_in; (void)out_size;
    const float* x = (const float*)d_in[0];
    const float* p[18];
    for (int i = 0; i < 18; i++) p[i] = (const float*)d_in[1 + i];
    // layer l: fwk=p[6l], fwr=p[6l+1], fwb=p[6l+2], bwk=p[6l+3], bwr=p[6l+4], bwb=p[6l+5]

    float* y    = (float*)d_out;                    // [B][T][512], inter-layer reuse
    float* hcat = y + (size_t)B_ * T_ * YCH;        // [B][512] final states

    cudaFuncSetAttribute(rec_kernel,
                         cudaFuncAttributeMaxDynamicSharedMemorySize,
                         REC_SMEM_BYTES);
    cudaFuncSetAttribute(gemm_xp_mma_kernel,
                         cudaFuncAttributeMaxDynamicSharedMemorySize,
                         GEMM_SMEM_BYTES);

    const int tot4 = B_*T_*X3/4;
    layer0_xp_kernel<<<(tot4 + 255)/256, 256>>>(x, p[0], p[2], p[3], p[5]);
    rec_kernel<<<128, REC_THREADS, REC_SMEM_BYTES>>>(p[1], p[2], p[4], p[5], y, hcat, 0);

    dim3 gg(X3/128, (B_*T_)/128, 2);
    gemm_xp_mma_kernel<<<gg, 256, GEMM_SMEM_BYTES>>>(y, p[6], p[8], p[9], p[11]);
    rec_kernel<<<128, REC_THREADS, REC_SMEM_BYTES>>>(p[7], p[8], p[10], p[11], y, hcat, 1);

    gemm_xp_mma_kernel<<<gg, 256, GEMM_SMEM_BYTES>>>(y, p[12], p[14], p[15], p[17]);
    rec_kernel<<<128, REC_THREADS, REC_SMEM_BYTES>>>(p[13], p[14], p[16], p[17], y, hcat, 2);
}

// round 12
// speedup vs baseline: 1.4526x; 1.4526x over previous
#include <cuda_runtime.h>
#include <cuda_bf16.h>
#include <cstdint>
#include <math.h>

#define U_  256
#define B_  32
#define T_  2048
#define X3  768      // 3U
#define YCH 512      // 2U
#define KP  272      // padded k-stride (272 mod 32 == 16 -> phase-split banks)
#define CL  4        // cluster size (ranks)
#define CPR 64       // columns per rank
#define BGR 2        // batch rows per cluster
#define REC_THREADS 512
// smem floats: mbar pad(4) + W(192*KP) + H(2*BGR*KP)   (no Red: shfl reduce)
#define SM_W    4
#define SM_H    (SM_W + 3*CPR*KP)
#define REC_SMEM_FLOATS (SM_H + 2*BGR*KP)
#define REC_SMEM_BYTES  (REC_SMEM_FLOATS*4)

// GEMM dynamic smem: 4 arrays x 2 stages x 128x40 halves
#define G_STG   5120                    // halves per array-stage
#define GEMM_SMEM_BYTES (8*G_STG*2)     // 81920 B

// Scratch: input projections per direction + inter-layer hidden states
__device__ float g_xp[2][B_*T_*X3];   // [dir][(b*T+t)*768 + c]
__device__ float g_h[2][B_][U_];      // final hidden state handoff between layers

// ---------------------------------------------------------------------------
// helpers
// ---------------------------------------------------------------------------
__device__ __forceinline__ uint32_t smem_u32(const void* p) {
    uint32_t a;
    asm("{ .reg .u64 t; cvta.to.shared.u64 t, %1; cvt.u32.u64 %0, t; }"
        : "=r"(a) : "l"(p));
    return a;
}
__device__ __forceinline__ uint32_t mapa_rank(uint32_t addr, int r) {
    uint32_t out;
    asm("mapa.shared::cluster.u32 %0, %1, %2;" : "=r"(out) : "r"(addr), "r"(r));
    return out;
}
__device__ __forceinline__ void st_cluster_f32(uint32_t addr, float v) {
    asm volatile("st.shared::cluster.f32 [%0], %1;" :: "r"(addr), "f"(v));
}
__device__ __forceinline__ uint32_t ctarank() {
    uint32_t r; asm("mov.u32 %0, %%cluster_ctarank;" : "=r"(r)); return r;
}
#define CLUSTER_ARRIVE_() asm volatile("barrier.cluster.arrive.aligned;" ::: "memory")
#define CLUSTER_WAIT_()   asm volatile("barrier.cluster.wait.aligned;"   ::: "memory")

__device__ __forceinline__ void mbar_init(uint32_t addr, uint32_t cnt) {
    asm volatile("mbarrier.init.shared.b64 [%0], %1;" :: "r"(addr), "r"(cnt) : "memory");
}
__device__ __forceinline__ void mbar_arrive_cluster(uint32_t addr) {
    asm volatile("mbarrier.arrive.release.cluster.shared::cluster.b64 _, [%0];"
                 :: "r"(addr) : "memory");
}
__device__ __forceinline__ void mbar_wait_parity(uint32_t addr, uint32_t parity) {
    asm volatile(
        "{\n\t"
        ".reg .pred P;\n\t"
        "WL%=:\n\t"
        "mbarrier.try_wait.parity.acquire.cluster.shared::cta.b64 P, [%0], %1, 0x989680;\n\t"
        "@!P bra WL%=;\n\t"
        "}"
        :: "r"(addr), "r"(parity) : "memory");
}

__device__ __forceinline__ float fast_sigmoid(float x) {
    return __fdividef(1.f, 1.f + __expf(-x));
}
__device__ __forceinline__ float fast_tanh(float x) {
    float e = __expf(-2.f * x);
    return __fdividef(1.f - e, 1.f + e);
}

// Packed dual fp32 FMA (Blackwell family, PTX ISA 8.6, sm_100+)
__device__ __forceinline__ void ffma2(unsigned long long& d,
                                      unsigned long long a,
                                      unsigned long long b) {
    asm("fma.rn.f32x2 %0, %1, %2, %0;" : "+l"(d) : "l"(a), "l"(b));
}
__device__ __forceinline__ float upk_sum(unsigned long long v) {
    float lo, hi;
    asm("mov.b64 {%0, %1}, %2;" : "=f"(lo), "=f"(hi) : "l"(v));
    return lo + hi;
}

// bf16 HMMA m16n8k16, fp32 accumulate (baseline PTX, legal on sm_100)
__device__ __forceinline__ void mma16816(float* c,
    uint32_t a0, uint32_t a1, uint32_t a2, uint32_t a3,
    uint32_t b0, uint32_t b1)
{
    asm volatile(
        "mma.sync.aligned.m16n8k16.row.col.f32.bf16.bf16.f32 "
        "{%0,%1,%2,%3}, {%4,%5,%6,%7}, {%8,%9}, {%0,%1,%2,%3};"
        : "+f"(c[0]), "+f"(c[1]), "+f"(c[2]), "+f"(c[3])
        : "r"(a0), "r"(a1), "r"(a2), "r"(a3), "r"(b0), "r"(b1));
}

// ---------------------------------------------------------------------------
// Layer 0 input projection: xp = x * Wk[0,:] + b[0,:]  (in_dim = 1)
// ---------------------------------------------------------------------------
__global__ void layer0_xp_kernel(const float* __restrict__ x,
                                 const float* __restrict__ fwk,
                                 const float* __restrict__ fwb,
                                 const float* __restrict__ bwk,
                                 const float* __restrict__ bwb)
{
    int i4 = blockIdx.x * blockDim.x + threadIdx.x;
    const int tot4 = B_*T_*X3/4;
    if (i4 >= tot4) return;
    int e  = i4 * 4;
    int c  = e % X3;
    int bt = e / X3;
    float xv = __ldg(&x[bt]);
    float4 kf = *(const float4*)&fwk[c];
    float4 bf = *(const float4*)&fwb[c];
    float4 kb = *(const float4*)&bwk[c];
    float4 bb = *(const float4*)&bwb[c];
    float4 of, ob;
    of.x = xv*kf.x + bf.x; of.y = xv*kf.y + bf.y;
    of.z = xv*kf.z + bf.z; of.w = xv*kf.w + bf.w;
    ob.x = xv*kb.x + bb.x; ob.y = xv*kb.y + bb.y;
    ob.z = xv*kb.z + bb.z; ob.w = xv*kb.w + bb.w;
    *(float4*)&g_xp[0][e] = of;
    *(float4*)&g_xp[1][e] = ob;
}

// ---------------------------------------------------------------------------
// Layers 1/2 input projection via bf16-split HMMA GEMM. (R10 DB version)
// ---------------------------------------------------------------------------
__global__ void __launch_bounds__(256) gemm_xp_mma_kernel(
    const float* __restrict__ Yin,
    const float* __restrict__ kfw, const float* __restrict__ bfw,
    const float* __restrict__ kbw, const float* __restrict__ bbw)
{
    extern __shared__ __nv_bfloat16 gsm[];

    int dir = blockIdx.z;
    const float* Wk   = dir ? kbw : kfw;
    const float* bias = dir ? bbw : bfw;   // row 0 = input bias
    float* out = g_xp[dir];

    int n0 = blockIdx.x * 128;
    int m0 = blockIdx.y * 128;

    int tid  = threadIdx.x;
    int lane = tid & 31, wid = tid >> 5;
    int wm = wid >> 2, wn = wid & 3;
    int gr = lane >> 2, tc = (lane & 3) * 2;

    int arow0 = tid >> 5;
    int ak    = tid & 31;
    int bk0   = tid >> 7;
    int bn    = tid & 127;

    float ra[16], rb[16];

    float acc[4][4][4];
#pragma unroll
    for (int i = 0; i < 4; i++)
#pragma unroll
        for (int j = 0; j < 4; j++)
#pragma unroll
            for (int q = 0; q < 4; q++) acc[i][j][q] = 0.f;

    // ---- stage kt=0 ----
    {
#pragma unroll
        for (int j = 0; j < 16; j++)
            ra[j] = __ldg(&Yin[(size_t)(m0 + arow0 + 8*j)*YCH + ak]);
#pragma unroll
        for (int j = 0; j < 16; j++)
            rb[j] = __ldg(&Wk[(size_t)(bk0 + 2*j)*X3 + n0 + bn]);
        __nv_bfloat16* pAh = gsm;
        __nv_bfloat16* pAl = gsm + 2*G_STG;
        __nv_bfloat16* pBh = gsm + 4*G_STG;
        __nv_bfloat16* pBl = gsm + 6*G_STG;
#pragma unroll
        for (int j = 0; j < 16; j++) {
            float v = ra[j];
            __nv_bfloat16 hi = __float2bfloat16(v);
            pAh[(arow0 + 8*j)*40 + ak] = hi;
            pAl[(arow0 + 8*j)*40 + ak] = __float2bfloat16(v - __bfloat162float(hi));
        }
#pragma unroll
        for (int j = 0; j < 16; j++) {
            float v = rb[j];
            __nv_bfloat16 hi = __float2bfloat16(v);
            pBh[bn*40 + bk0 + 2*j] = hi;
            pBl[bn*40 + bk0 + 2*j] = __float2bfloat16(v - __bfloat162float(hi));
        }
    }
    __syncthreads();

    for (int kt = 0; kt < 16; kt++) {
        int cur = kt & 1;
        if (kt < 15) {
            int kc = (kt + 1) * 32;
#pragma unroll
            for (int j = 0; j < 16; j++)
                ra[j] = __ldg(&Yin[(size_t)(m0 + arow0 + 8*j)*YCH + kc + ak]);
#pragma unroll
            for (int j = 0; j < 16; j++)
                rb[j] = __ldg(&Wk[(size_t)(kc + bk0 + 2*j)*X3 + n0 + bn]);
        }

        const __nv_bfloat16* pAh = gsm +            cur*G_STG;
        const __nv_bfloat16* pAl = gsm + 2*G_STG +  cur*G_STG;
        const __nv_bfloat16* pBh = gsm + 4*G_STG +  cur*G_STG;
        const __nv_bfloat16* pBl = gsm + 6*G_STG +  cur*G_STG;

#pragma unroll
        for (int kk = 0; kk < 32; kk += 16) {
            uint32_t fbh[4][2], fbl[4][2];
#pragma unroll
            for (int nf = 0; nf < 4; nf++) {
                int n = wn*32 + nf*8 + gr;
                fbh[nf][0] = *(const uint32_t*)&pBh[n*40 + kk + tc];
                fbh[nf][1] = *(const uint32_t*)&pBh[n*40 + kk + tc + 8];
                fbl[nf][0] = *(const uint32_t*)&pBl[n*40 + kk + tc];
                fbl[nf][1] = *(const uint32_t*)&pBl[n*40 + kk + tc + 8];
            }
            uint32_t fah[4][4], fal[4][4];
#pragma unroll
            for (int mf = 0; mf < 4; mf++) {
                int r = wm*64 + mf*16 + gr;
                fah[mf][0] = *(const uint32_t*)&pAh[(r    )*40 + kk + tc];
                fah[mf][1] = *(const uint32_t*)&pAh[(r + 8)*40 + kk + tc];
                fah[mf][2] = *(const uint32_t*)&pAh[(r    )*40 + kk + tc + 8];
                fah[mf][3] = *(const uint32_t*)&pAh[(r + 8)*40 + kk + tc + 8];
                fal[mf][0] = *(const uint32_t*)&pAl[(r    )*40 + kk + tc];
                fal[mf][1] = *(const uint32_t*)&pAl[(r + 8)*40 + kk + tc];
                fal[mf][2] = *(const uint32_t*)&pAl[(r    )*40 + kk + tc + 8];
                fal[mf][3] = *(const uint32_t*)&pAl[(r + 8)*40 + kk + tc + 8];
            }
#pragma unroll
            for (int mf = 0; mf < 4; mf++)
#pragma unroll
                for (int nf = 0; nf < 4; nf++)
                    mma16816(acc[mf][nf], fah[mf][0], fah[mf][1], fah[mf][2],
                             fah[mf][3], fbh[nf][0], fbh[nf][1]);
#pragma unroll
            for (int mf = 0; mf < 4; mf++)
#pragma unroll
                for (int nf = 0; nf < 4; nf++)
                    mma16816(acc[mf][nf], fal[mf][0], fal[mf][1], fal[mf][2],
                             fal[mf][3], fbh[nf][0], fbh[nf][1]);
#pragma unroll
            for (int mf = 0; mf < 4; mf++)
#pragma unroll
                for (int nf = 0; nf < 4; nf++)
                    mma16816(acc[mf][nf], fah[mf][0], fah[mf][1], fah[mf][2],
                             fah[mf][3], fbl[nf][0], fbl[nf][1]);
        }

        if (kt < 15) {
            int nxt = cur ^ 1;
            __nv_bfloat16* qAh = gsm +            nxt*G_STG;
            __nv_bfloat16* qAl = gsm + 2*G_STG +  nxt*G_STG;
            __nv_bfloat16* qBh = gsm + 4*G_STG +  nxt*G_STG;
            __nv_bfloat16* qBl = gsm + 6*G_STG +  nxt*G_STG;
#pragma unroll
            for (int j = 0; j < 16; j++) {
                float v = ra[j];
                __nv_bfloat16 hi = __float2bfloat16(v);
                qAh[(arow0 + 8*j)*40 + ak] = hi;
                qAl[(arow0 + 8*j)*40 + ak] = __float2bfloat16(v - __bfloat162float(hi));
            }
#pragma unroll
            for (int j = 0; j < 16; j++) {
                float v = rb[j];
                __nv_bfloat16 hi = __float2bfloat16(v);
                qBh[bn*40 + bk0 + 2*j] = hi;
                qBl[bn*40 + bk0 + 2*j] = __float2bfloat16(v - __bfloat162float(hi));
            }
        }
        __syncthreads();
    }

    // Epilogue
#pragma unroll
    for (int mf = 0; mf < 4; mf++) {
        int row = m0 + wm*64 + mf*16 + gr;
#pragma unroll
        for (int nf = 0; nf < 4; nf++) {
            int col = n0 + wn*32 + nf*8 + tc;
            float b0 = __ldg(&bias[col]), b1 = __ldg(&bias[col + 1]);
            float2 lo, hi;
            lo.x = acc[mf][nf][0] + b0; lo.y = acc[mf][nf][1] + b1;
            hi.x = acc[mf][nf][2] + b0; hi.y = acc[mf][nf][3] + b1;
            *(float2*)&out[(size_t)row * X3 + col]       = lo;
            *(float2*)&out[(size_t)(row + 8) * X3 + col] = hi;
        }
    }
}

// ---------------------------------------------------------------------------
// Recurrence. Grid = 128 CTAs, clusters of 4, 512 threads. (CL=8 reverted)
//   R12: quad-per-group lane mapping — the 4 k-quarters of each (jl,bl) sit
//   in one warp quad (lane = g*4 + kh, k interleaved in 16B chunks), so the
//   cross-kh reduction is 2 shfl.xor instead of smem Red + __syncthreads.
//   KP=272 (mod 32 == 16) keeps every 8-lane phase bank-conflict-free.
//   Step protocol (barrier #2, remote arrives, parity wait) identical to R10.
// ---------------------------------------------------------------------------
__global__ void __cluster_dims__(CL, 1, 1) __launch_bounds__(REC_THREADS, 1)
rec_kernel(const float* __restrict__ wr_fw, const float* __restrict__ bias_fw,
           const float* __restrict__ wr_bw, const float* __restrict__ bias_bw,
           float* __restrict__ y, float* __restrict__ hcat, int layer)
{
    extern __shared__ float sm[];
    float* Wsm = sm + SM_W;          // [192][KP]
    float* Hsm = sm + SM_H;          // [2][BGR][KP]
    uint32_t mbar = smem_u32(sm);    // 8B mbarrier at sm[0..1]

    int rank = (int)ctarank();
    int cidx = blockIdx.x >> 2;       // 0..31
    int dir  = cidx >> 4;             // 0 fw, 1 bw
    int bg   = cidx & 15;             // batch group (2 rows)
    int tid  = threadIdx.x;
    int warp = tid >> 5;
    int lane = tid & 31;
    int g    = lane >> 2;             // group in warp 0..7
    int kh   = lane & 3;              // k-quarter
    int grp  = warp*8 + g;            // 0..127
    int jl   = grp >> 1;              // 0..63 local column
    int bl   = grp & 1;               // 0..1 local batch
    int jglob = rank*CPR + jl;
    int bglob = bg*BGR + bl;

    const float* Wr   = dir ? wr_bw   : wr_fw;
    const float* bias = dir ? bias_bw : bias_fw;
    const float* xp   = g_xp[dir];

    if (tid == 0) mbar_init(mbar, CL);

    // Load weight slice: Wsm[(gate*64+j)*KP + k] = Wr[k][gate*256 + rank*64 + j]
    for (int idx = tid; idx < 192*256; idx += REC_THREADS) {
        int k    = idx / 192;
        int r192 = idx - k*192;
        int gt = r192 >> 6, j = r192 & 63;
        Wsm[(gt*CPR + j)*KP + k] = __ldg(&Wr[k*X3 + gt*256 + rank*CPR + j]);
    }
    // Initial hidden state into parity-0 buffer
    for (int i = tid; i < BGR*256; i += REC_THREADS) {
        int b = i >> 8, k = i & 255;
        Hsm[b*KP + k] = layer ? g_h[dir][bg*BGR + b][k] : 0.f;
    }
    // Recurrent biases — only needed by kh==0 lanes
    float bz = 0.f, br = 0.f, bh = 0.f;
    if (kh == 0) {
        bz = __ldg(&bias[X3 +       jglob]);
        br = __ldg(&bias[X3 + 256 + jglob]);
        bh = __ldg(&bias[X3 + 512 + jglob]);
    }
    __syncthreads();
    CLUSTER_ARRIVE_();   // all mbarriers initialised + H/W loaded cluster-wide
    CLUSTER_WAIT_();

    uint32_t hbase = smem_u32(Hsm);
    uint32_t peerH[CL], peerM[CL];
#pragma unroll
    for (int r = 0; r < CL; r++) {
        peerH[r] = mapa_rank(hbase, r);
        peerM[r] = mapa_rank(mbar, r);
    }
    uint32_t off_self = (uint32_t)((bl*KP + jglob) * 4);

    // packed-pair views; k-chunk index = kh + 4*i (16B interleave)
    const ulonglong2* wz2 = (const ulonglong2*)(Wsm + (          jl)*KP);
    const ulonglong2* wr2 = (const ulonglong2*)(Wsm + ( CPR    + jl)*KP);
    const ulonglong2* wh2 = (const ulonglong2*)(Wsm + (2*CPR   + jl)*KP);

    // h(t-1) carried in-register by kh==0 lanes
    float hn = (kh == 0) ? Hsm[bl*KP + jglob] : 0.f;

    // prefetch xp for step 0
    float xz = 0.f, xr = 0.f, xh = 0.f;
    if (kh == 0) {
        int tt0 = dir ? (T_-1) : 0;
        size_t xrow = ((size_t)bglob*T_ + tt0) * X3;
        xz = __ldg(&xp[xrow +       jglob]);
        xr = __ldg(&xp[xrow + 256 + jglob]);
        xh = __ldg(&xp[xrow + 512 + jglob]);
    }

    int p = 0;
    for (int s = 0; s < T_; s++) {
        int tt = dir ? (T_-1-s) : s;

        const ulonglong2* hv2 = (const ulonglong2*)(Hsm + (p*BGR + bl)*KP);
        unsigned long long az0 = 0ull, az1 = 0ull;
        unsigned long long ar0 = 0ull, ar1 = 0ull;
        unsigned long long ah0 = 0ull, ah1 = 0ull;
#pragma unroll
        for (int i = 0; i < 16; i++) {
            int k4 = kh + 4*i;
            ulonglong2 h2 = hv2[k4];
            ulonglong2 w;
            w = wz2[k4]; ffma2(az0, w.x, h2.x); ffma2(az1, w.y, h2.y);
            w = wr2[k4]; ffma2(ar0, w.x, h2.x); ffma2(ar1, w.y, h2.y);
            w = wh2[k4]; ffma2(ah0, w.x, h2.x); ffma2(ah1, w.y, h2.y);
        }
        float pz = upk_sum(az0) + upk_sum(az1);
        float pr = upk_sum(ar0) + upk_sum(ar1);
        float ph = upk_sum(ah0) + upk_sum(ah1);

        // quad reduction over kh (lanes differing in bits 0,1)
        pz += __shfl_xor_sync(0xFFFFFFFF, pz, 1);
        pr += __shfl_xor_sync(0xFFFFFFFF, pr, 1);
        ph += __shfl_xor_sync(0xFFFFFFFF, ph, 1);
        pz += __shfl_xor_sync(0xFFFFFFFF, pz, 2);
        pr += __shfl_xor_sync(0xFFFFFFFF, pr, 2);
        ph += __shfl_xor_sync(0xFFFFFFFF, ph, 2);

        if (kh == 0) {
            float hz = pz + bz;
            float hr = pr + br;
            float hh = ph + bh;
            float z    = fast_sigmoid(xz + hz);
            float r    = fast_sigmoid(xr + hr);
            float cand = fast_tanh(xh + r * hh);
            hn = fmaf(z, hn - cand, cand);      // z*h + (1-z)*cand

            // push to next-parity h buffer of every rank (incl. self)
            uint32_t off = off_self + (uint32_t)((p ^ 1) * BGR * KP * 4);
#pragma unroll
            for (int rr = 0; rr < CL; rr++) st_cluster_f32(peerH[rr] + off, hn);
        }

        __syncthreads();                 // all pushes issued CTA-wide
        if (tid < CL) mbar_arrive_cluster(peerM[tid]);

        // latency cover between arrive and wait: y store + next-x prefetch
        if (kh == 0) {
            y[((size_t)bglob*T_ + tt)*YCH + dir*256 + jglob] = hn;
            if (s + 1 < T_) {
                int tn = dir ? (T_-2-s) : (s+1);
                size_t xrow = ((size_t)bglob*T_ + tn) * X3;
                xz = __ldg(&xp[xrow +       jglob]);
                xr = __ldg(&xp[xrow + 256 + jglob]);
                xh = __ldg(&xp[xrow + 512 + jglob]);
            }
        }

        mbar_wait_parity(mbar, (uint32_t)(s & 1));
        p ^= 1;
    }

    if (kh == 0) {
        if (layer == 2)
            hcat[(size_t)bglob*YCH + dir*256 + jglob] = hn;
        else
            g_h[dir][bglob][jglob] = hn;
    }
    CLUSTER_ARRIVE_();   // keep smem alive until all peers' final pushes land
    CLUSTER_WAIT_();
}

// ---------------------------------------------------------------------------
// launch
// ---------------------------------------------------------------------------
extern "C" void kernel_launch(void* const* d_in, const int* in_sizes, int n_in,
                              void* d_out, int out_size)
{
    (void)in_sizes; (void)n_in; (void)out_size;
    const float* x = (const float*)d_in[0];
    const float* p[18];
    for (int i = 0; i < 18; i++) p[i] = (const float*)d_in[1 + i];
    // layer l: fwk=p[6l], fwr=p[6l+1], fwb=p[6l+2], bwk=p[6l+3], bwr=p[6l+4], bwb=p[6l+5]

    float* y    = (float*)d_out;                    // [B][T][512], inter-layer reuse
    float* hcat = y + (size_t)B_ * T_ * YCH;        // [B][512] final states

    cudaFuncSetAttribute(rec_kernel,
                         cudaFuncAttributeMaxDynamicSharedMemorySize,
                         REC_SMEM_BYTES);
    cudaFuncSetAttribute(gemm_xp_mma_kernel,
                         cudaFuncAttributeMaxDynamicSharedMemorySize,
                         GEMM_SMEM_BYTES);

    const int tot4 = B_*T_*X3/4;
    layer0_xp_kernel<<<(tot4 + 255)/256, 256>>>(x, p[0], p[2], p[3], p[5]);
    rec_kernel<<<128, REC_THREADS, REC_SMEM_BYTES>>>(p[1], p[2], p[4], p[5], y, hcat, 0);

    dim3 gg(X3/128, (B_*T_)/128, 2);
    gemm_xp_mma_kernel<<<gg, 256, GEMM_SMEM_BYTES>>>(y, p[6], p[8], p[9], p[11]);
    rec_kernel<<<128, REC_THREADS, REC_SMEM_BYTES>>>(p[7], p[8], p[10], p[11], y, hcat, 1);

    gemm_xp_mma_kernel<<<gg, 256, GEMM_SMEM_BYTES>>>(y, p[12], p[14], p[15], p[17]);
    rec_kernel<<<128, REC_THREADS, REC_SMEM_BYTES>>>(p[13], p[14], p[16], p[17], y, hcat, 2);
}

// round 13
// speedup vs baseline: 2.1901x; 1.5077x over previous
#include <cuda_runtime.h>
#include <cuda_bf16.h>
#include <cstdint>
#include <math.h>

#define U_  256
#define B_  32
#define T_  2048
#define X3  768      // 3U
#define YCH 512      // 2U
#define KP  260      // padded k-stride (R10 proven)
#define CL  4        // cluster size (ranks)
#define CPR 64       // columns per rank
#define BGR 2        // batch rows per cluster
#define REC_THREADS 512
// smem floats: mbar pad(4) + W(192*KP) + H(2*BGR*KP) + Red(3*128*4)
#define SM_W    4
#define SM_H    (SM_W + 192*KP)
#define SM_RED  (SM_H + 2*BGR*KP)
#define REC_SMEM_FLOATS (SM_RED + 3*128*4)
#define REC_SMEM_BYTES  (REC_SMEM_FLOATS*4)

// GEMM dynamic smem: 4 arrays x 2 stages x 128x40 halves
#define G_STG   5120                    // halves per array-stage
#define GEMM_SMEM_BYTES (8*G_STG*2)     // 81920 B

// Scratch: input projections per direction + inter-layer hidden states
__device__ float g_xp[2][B_*T_*X3];   // [dir][(b*T+t)*768 + c]
__device__ float g_h[2][B_][U_];      // final hidden state handoff between layers

// ---------------------------------------------------------------------------
// helpers
// ---------------------------------------------------------------------------
__device__ __forceinline__ uint32_t smem_u32(const void* p) {
    uint32_t a;
    asm("{ .reg .u64 t; cvta.to.shared.u64 t, %1; cvt.u32.u64 %0, t; }"
        : "=r"(a) : "l"(p));
    return a;
}
__device__ __forceinline__ uint32_t mapa_rank(uint32_t addr, int r) {
    uint32_t out;
    asm("mapa.shared::cluster.u32 %0, %1, %2;" : "=r"(out) : "r"(addr), "r"(r));
    return out;
}
__device__ __forceinline__ void st_cluster_f32(uint32_t addr, float v) {
    asm volatile("st.shared::cluster.f32 [%0], %1;" :: "r"(addr), "f"(v));
}
__device__ __forceinline__ uint32_t ctarank() {
    uint32_t r; asm("mov.u32 %0, %%cluster_ctarank;" : "=r"(r)); return r;
}
#define CLUSTER_ARRIVE_() asm volatile("barrier.cluster.arrive.aligned;" ::: "memory")
#define CLUSTER_WAIT_()   asm volatile("barrier.cluster.wait.aligned;"   ::: "memory")

__device__ __forceinline__ void mbar_init(uint32_t addr, uint32_t cnt) {
    asm volatile("mbarrier.init.shared.b64 [%0], %1;" :: "r"(addr), "r"(cnt) : "memory");
}
__device__ __forceinline__ void mbar_arrive_cluster(uint32_t addr) {
    asm volatile("mbarrier.arrive.release.cluster.shared::cluster.b64 _, [%0];"
                 :: "r"(addr) : "memory");
}
__device__ __forceinline__ void mbar_wait_parity(uint32_t addr, uint32_t parity) {
    asm volatile(
        "{\n\t"
        ".reg .pred P;\n\t"
        "WL%=:\n\t"
        "mbarrier.try_wait.parity.acquire.cluster.shared::cta.b64 P, [%0], %1, 0x989680;\n\t"
        "@!P bra WL%=;\n\t"
        "}"
        :: "r"(addr), "r"(parity) : "memory");
}

__device__ __forceinline__ float fast_sigmoid(float x) {
    return __fdividef(1.f, 1.f + __expf(-x));
}
__device__ __forceinline__ float fast_tanh(float x) {
    float e = __expf(-2.f * x);
    return __fdividef(1.f - e, 1.f + e);
}

// Packed dual fp32 FMA (Blackwell family, PTX ISA 8.6, sm_100+)
__device__ __forceinline__ void ffma2(unsigned long long& d,
                                      unsigned long long a,
                                      unsigned long long b) {
    asm("fma.rn.f32x2 %0, %1, %2, %0;" : "+l"(d) : "l"(a), "l"(b));
}
__device__ __forceinline__ float upk_sum(unsigned long long v) {
    float lo, hi;
    asm("mov.b64 {%0, %1}, %2;" : "=f"(lo), "=f"(hi) : "l"(v));
    return lo + hi;
}

// bf16 HMMA m16n8k16, fp32 accumulate (baseline PTX, legal on sm_100)
__device__ __forceinline__ void mma16816(float* c,
    uint32_t a0, uint32_t a1, uint32_t a2, uint32_t a3,
    uint32_t b0, uint32_t b1)
{
    asm volatile(
        "mma.sync.aligned.m16n8k16.row.col.f32.bf16.bf16.f32 "
        "{%0,%1,%2,%3}, {%4,%5,%6,%7}, {%8,%9}, {%0,%1,%2,%3};"
        : "+f"(c[0]), "+f"(c[1]), "+f"(c[2]), "+f"(c[3])
        : "r"(a0), "r"(a1), "r"(a2), "r"(a3), "r"(b0), "r"(b1));
}

// split one fp32 pair into hi/lo bf16x2 (hi = rn(v), lo = rn(v - hi))
__device__ __forceinline__ void split_pair(float x, float y,
                                           __nv_bfloat162& hi2,
                                           __nv_bfloat162& lo2)
{
    hi2 = __floats2bfloat162_rn(x, y);
    float lx = x - __bfloat162float(__low2bfloat16(hi2));
    float ly = y - __bfloat162float(__high2bfloat16(hi2));
    lo2 = __floats2bfloat162_rn(lx, ly);
}

// ---------------------------------------------------------------------------
// Layer 0 input projection: xp = x * Wk[0,:] + b[0,:]  (in_dim = 1)
// ---------------------------------------------------------------------------
__global__ void layer0_xp_kernel(const float* __restrict__ x,
                                 const float* __restrict__ fwk,
                                 const float* __restrict__ fwb,
                                 const float* __restrict__ bwk,
                                 const float* __restrict__ bwb)
{
    int i4 = blockIdx.x * blockDim.x + threadIdx.x;
    const int tot4 = B_*T_*X3/4;
    if (i4 >= tot4) return;
    int e  = i4 * 4;
    int c  = e % X3;
    int bt = e / X3;
    float xv = __ldg(&x[bt]);
    float4 kf = *(const float4*)&fwk[c];
    float4 bf = *(const float4*)&fwb[c];
    float4 kb = *(const float4*)&bwk[c];
    float4 bb = *(const float4*)&bwb[c];
    float4 of, ob;
    of.x = xv*kf.x + bf.x; of.y = xv*kf.y + bf.y;
    of.z = xv*kf.z + bf.z; of.w = xv*kf.w + bf.w;
    ob.x = xv*kb.x + bb.x; ob.y = xv*kb.y + bb.y;
    ob.z = xv*kb.z + bb.z; ob.w = xv*kb.w + bb.w;
    *(float4*)&g_xp[0][e] = of;
    *(float4*)&g_xp[1][e] = ob;
}

// ---------------------------------------------------------------------------
// Layers 1/2 input projection via bf16-split HMMA GEMM.
//   R13: packed bf16x2 smem staging — 32-bit STS instead of 16-bit,
//   halving store instructions. Same layout/fragments/MMA as R10.
// ---------------------------------------------------------------------------
__global__ void __launch_bounds__(256) gemm_xp_mma_kernel(
    const float* __restrict__ Yin,
    const float* __restrict__ kfw, const float* __restrict__ bfw,
    const float* __restrict__ kbw, const float* __restrict__ bbw)
{
    extern __shared__ __nv_bfloat16 gsm[];

    int dir = blockIdx.z;
    const float* Wk   = dir ? kbw : kfw;
    const float* bias = dir ? bbw : bfw;   // row 0 = input bias
    float* out = g_xp[dir];

    int n0 = blockIdx.x * 128;
    int m0 = blockIdx.y * 128;

    int tid  = threadIdx.x;
    int lane = tid & 31, wid = tid >> 5;
    int wm = wid >> 2, wn = wid & 3;
    int gr = lane >> 2, tc = (lane & 3) * 2;

    // A staging: idx = tid + 256j (j<8), row = idx>>4, kk2 = (idx&15)*2
    int a_row0 = tid >> 4;          // + 16j
    int a_k2   = (tid & 15) * 2;
    // B staging: n = tid&127, kpair base = (tid>>7)*2, k = base + 4j (j<8)
    int b_n  = tid & 127;
    int b_kp = (tid >> 7) * 2;

    float2 ra[8];
    float  rb0[8], rb1[8];

    float acc[4][4][4];
#pragma unroll
    for (int i = 0; i < 4; i++)
#pragma unroll
        for (int j = 0; j < 4; j++)
#pragma unroll
            for (int q = 0; q < 4; q++) acc[i][j][q] = 0.f;

    // ---- stage kt=0 ----
    {
#pragma unroll
        for (int j = 0; j < 8; j++)
            ra[j] = *(const float2*)&Yin[(size_t)(m0 + a_row0 + 16*j)*YCH + a_k2];
#pragma unroll
        for (int j = 0; j < 8; j++) {
            int k = b_kp + 4*j;
            rb0[j] = __ldg(&Wk[(size_t)k*X3 + n0 + b_n]);
            rb1[j] = __ldg(&Wk[(size_t)(k+1)*X3 + n0 + b_n]);
        }
        __nv_bfloat16* pAh = gsm;
        __nv_bfloat16* pAl = gsm + 2*G_STG;
        __nv_bfloat16* pBh = gsm + 4*G_STG;
        __nv_bfloat16* pBl = gsm + 6*G_STG;
#pragma unroll
        for (int j = 0; j < 8; j++) {
            __nv_bfloat162 h2, l2;
            split_pair(ra[j].x, ra[j].y, h2, l2);
            int off = (a_row0 + 16*j)*40 + a_k2;
            *(__nv_bfloat162*)&pAh[off] = h2;
            *(__nv_bfloat162*)&pAl[off] = l2;
        }
#pragma unroll
        for (int j = 0; j < 8; j++) {
            __nv_bfloat162 h2, l2;
            split_pair(rb0[j], rb1[j], h2, l2);
            int off = b_n*40 + b_kp + 4*j;
            *(__nv_bfloat162*)&pBh[off] = h2;
            *(__nv_bfloat162*)&pBl[off] = l2;
        }
    }
    __syncthreads();

    for (int kt = 0; kt < 16; kt++) {
        int cur = kt & 1;
        if (kt < 15) {
            int kc = (kt + 1) * 32;
#pragma unroll
            for (int j = 0; j < 8; j++)
                ra[j] = *(const float2*)&Yin[(size_t)(m0 + a_row0 + 16*j)*YCH + kc + a_k2];
#pragma unroll
            for (int j = 0; j < 8; j++) {
                int k = kc + b_kp + 4*j;
                rb0[j] = __ldg(&Wk[(size_t)k*X3 + n0 + b_n]);
                rb1[j] = __ldg(&Wk[(size_t)(k+1)*X3 + n0 + b_n]);
            }
        }

        const __nv_bfloat16* pAh = gsm +            cur*G_STG;
        const __nv_bfloat16* pAl = gsm + 2*G_STG +  cur*G_STG;
        const __nv_bfloat16* pBh = gsm + 4*G_STG +  cur*G_STG;
        const __nv_bfloat16* pBl = gsm + 6*G_STG +  cur*G_STG;

#pragma unroll
        for (int kk = 0; kk < 32; kk += 16) {
            uint32_t fbh[4][2], fbl[4][2];
#pragma unroll
            for (int nf = 0; nf < 4; nf++) {
                int n = wn*32 + nf*8 + gr;
                fbh[nf][0] = *(const uint32_t*)&pBh[n*40 + kk + tc];
                fbh[nf][1] = *(const uint32_t*)&pBh[n*40 + kk + tc + 8];
                fbl[nf][0] = *(const uint32_t*)&pBl[n*40 + kk + tc];
                fbl[nf][1] = *(const uint32_t*)&pBl[n*40 + kk + tc + 8];
            }
            uint32_t fah[4][4], fal[4][4];
#pragma unroll
            for (int mf = 0; mf < 4; mf++) {
                int r = wm*64 + mf*16 + gr;
                fah[mf][0] = *(const uint32_t*)&pAh[(r    )*40 + kk + tc];
                fah[mf][1] = *(const uint32_t*)&pAh[(r + 8)*40 + kk + tc];
                fah[mf][2] = *(const uint32_t*)&pAh[(r    )*40 + kk + tc + 8];
                fah[mf][3] = *(const uint32_t*)&pAh[(r + 8)*40 + kk + tc + 8];
                fal[mf][0] = *(const uint32_t*)&pAl[(r    )*40 + kk + tc];
                fal[mf][1] = *(const uint32_t*)&pAl[(r + 8)*40 + kk + tc];
                fal[mf][2] = *(const uint32_t*)&pAl[(r    )*40 + kk + tc + 8];
                fal[mf][3] = *(const uint32_t*)&pAl[(r + 8)*40 + kk + tc + 8];
            }
#pragma unroll
            for (int mf = 0; mf < 4; mf++)
#pragma unroll
                for (int nf = 0; nf < 4; nf++)
                    mma16816(acc[mf][nf], fah[mf][0], fah[mf][1], fah[mf][2],
                             fah[mf][3], fbh[nf][0], fbh[nf][1]);
#pragma unroll
            for (int mf = 0; mf < 4; mf++)
#pragma unroll
                for (int nf = 0; nf < 4; nf++)
                    mma16816(acc[mf][nf], fal[mf][0], fal[mf][1], fal[mf][2],
                             fal[mf][3], fbh[nf][0], fbh[nf][1]);
#pragma unroll
            for (int mf = 0; mf < 4; mf++)
#pragma unroll
                for (int nf = 0; nf < 4; nf++)
                    mma16816(acc[mf][nf], fah[mf][0], fah[mf][1], fah[mf][2],
                             fah[mf][3], fbl[nf][0], fbl[nf][1]);
        }

        if (kt < 15) {
            int nxt = cur ^ 1;
            __nv_bfloat16* qAh = gsm +            nxt*G_STG;
            __nv_bfloat16* qAl = gsm + 2*G_STG +  nxt*G_STG;
            __nv_bfloat16* qBh = gsm + 4*G_STG +  nxt*G_STG;
            __nv_bfloat16* qBl = gsm + 6*G_STG +  nxt*G_STG;
#pragma unroll
            for (int j = 0; j < 8; j++) {
                __nv_bfloat162 h2, l2;
                split_pair(ra[j].x, ra[j].y, h2, l2);
                int off = (a_row0 + 16*j)*40 + a_k2;
                *(__nv_bfloat162*)&qAh[off] = h2;
                *(__nv_bfloat162*)&qAl[off] = l2;
            }
#pragma unroll
            for (int j = 0; j < 8; j++) {
                __nv_bfloat162 h2, l2;
                split_pair(rb0[j], rb1[j], h2, l2);
                int off = b_n*40 + b_kp + 4*j;
                *(__nv_bfloat162*)&qBh[off] = h2;
                *(__nv_bfloat162*)&qBl[off] = l2;
            }
        }
        __syncthreads();
    }

    // Epilogue
#pragma unroll
    for (int mf = 0; mf < 4; mf++) {
        int row = m0 + wm*64 + mf*16 + gr;
#pragma unroll
        for (int nf = 0; nf < 4; nf++) {
            int col = n0 + wn*32 + nf*8 + tc;
            float b0 = __ldg(&bias[col]), b1 = __ldg(&bias[col + 1]);
            float2 lo, hi;
            lo.x = acc[mf][nf][0] + b0; lo.y = acc[mf][nf][1] + b1;
            hi.x = acc[mf][nf][2] + b0; hi.y = acc[mf][nf][3] + b1;
            *(float2*)&out[(size_t)row * X3 + col]       = lo;
            *(float2*)&out[(size_t)(row + 8) * X3 + col] = hi;
        }
    }
}

// ---------------------------------------------------------------------------
// Recurrence. Grid = 128 CTAs, clusters of 4, 512 threads.
//   BYTE-IDENTICAL to the proven R10 version (14548 us). Do not touch.
// ---------------------------------------------------------------------------
__global__ void __cluster_dims__(CL, 1, 1) __launch_bounds__(REC_THREADS, 1)
rec_kernel(const float* __restrict__ wr_fw, const float* __restrict__ bias_fw,
           const float* __restrict__ wr_bw, const float* __restrict__ bias_bw,
           float* __restrict__ y, float* __restrict__ hcat, int layer)
{
    extern __shared__ float sm[];
    float* Wsm = sm + SM_W;          // [192][KP]
    float* Hsm = sm + SM_H;          // [2][BGR][KP]
    float* Red = sm + SM_RED;        // [3][128][4]
    uint32_t mbar = smem_u32(sm);    // 8B mbarrier at sm[0..1]

    int rank = (int)ctarank();
    int cidx = blockIdx.x >> 2;       // 0..31
    int dir  = cidx >> 4;             // 0 fw, 1 bw
    int bg   = cidx & 15;             // batch group (2 rows)
    int tid  = threadIdx.x;
    int kh   = tid >> 7;              // k-quarter 0..3
    int tl   = tid & 127;
    int jl   = tl >> 1;               // 0..63 local column
    int bl   = tl & 1;                // 0..1 local batch
    int jglob = rank*CPR + jl;
    int bglob = bg*BGR + bl;

    const float* Wr   = dir ? wr_bw   : wr_fw;
    const float* bias = dir ? bias_bw : bias_fw;
    const float* xp   = g_xp[dir];

    if (tid == 0) mbar_init(mbar, CL);

    // Load weight slice: Wsm[(g*64+j)*KP + k] = Wr[k][g*256 + rank*64 + j]
    for (int idx = tid; idx < 192*256; idx += REC_THREADS) {
        int k    = idx / 192;
        int r192 = idx - k*192;
        int g = r192 >> 6, j = r192 & 63;
        Wsm[(g*CPR + j)*KP + k] = __ldg(&Wr[k*X3 + g*256 + rank*CPR + j]);
    }
    // Initial hidden state into parity-0 buffer
    for (int i = tid; i < BGR*256; i += REC_THREADS) {
        int b = i >> 8, k = i & 255;
        Hsm[b*KP + k] = layer ? g_h[dir][bg*BGR + b][k] : 0.f;
    }
    // Recurrent biases (row 1 of bias array) — only needed by kh=0
    float bz = 0.f, br = 0.f, bh = 0.f;
    if (kh == 0) {
        bz = __ldg(&bias[X3 +       jglob]);
        br = __ldg(&bias[X3 + 256 + jglob]);
        bh = __ldg(&bias[X3 + 512 + jglob]);
    }
    __syncthreads();
    CLUSTER_ARRIVE_();   // all mbarriers initialised + H/W loaded cluster-wide
    CLUSTER_WAIT_();

    uint32_t hbase = smem_u32(Hsm);
    uint32_t peerH[CL], peerM[CL];
#pragma unroll
    for (int r = 0; r < CL; r++) {
        peerH[r] = mapa_rank(hbase, r);
        peerM[r] = mapa_rank(mbar, r);
    }
    uint32_t off_self = (uint32_t)((bl*KP + jglob) * 4);

    // packed-pair views of weight rows (16B = 2 x f32x2 lanes)
    const ulonglong2* wz2 = (const ulonglong2*)(Wsm + (          jl)*KP) + kh*16;
    const ulonglong2* wr2 = (const ulonglong2*)(Wsm + ( CPR    + jl)*KP) + kh*16;
    const ulonglong2* wh2 = (const ulonglong2*)(Wsm + (2*CPR   + jl)*KP) + kh*16;

    // h(t-1) for this (jglob,bl) carried in-register by kh==0 threads
    float hn = (kh == 0) ? Hsm[bl*KP + jglob] : 0.f;

    // prefetch xp for step 0
    float xz = 0.f, xr = 0.f, xh = 0.f;
    if (kh == 0) {
        int tt0 = dir ? (T_-1) : 0;
        size_t xrow = ((size_t)bglob*T_ + tt0) * X3;
        xz = __ldg(&xp[xrow +       jglob]);
        xr = __ldg(&xp[xrow + 256 + jglob]);
        xh = __ldg(&xp[xrow + 512 + jglob]);
    }

    int p = 0;
    for (int s = 0; s < T_; s++) {
        int tt = dir ? (T_-1-s) : s;

        const ulonglong2* hv2 =
            (const ulonglong2*)(Hsm + (p*BGR + bl)*KP) + kh*16;
        unsigned long long az0 = 0ull, az1 = 0ull;
        unsigned long long ar0 = 0ull, ar1 = 0ull;
        unsigned long long ah0 = 0ull, ah1 = 0ull;
#pragma unroll
        for (int k4 = 0; k4 < 16; k4++) {
            ulonglong2 h2 = hv2[k4];
            ulonglong2 w;
            w = wz2[k4]; ffma2(az0, w.x, h2.x); ffma2(az1, w.y, h2.y);
            w = wr2[k4]; ffma2(ar0, w.x, h2.x); ffma2(ar1, w.y, h2.y);
            w = wh2[k4]; ffma2(ah0, w.x, h2.x); ffma2(ah1, w.y, h2.y);
        }
        float pz = upk_sum(az0) + upk_sum(az1);
        float pr = upk_sum(ar0) + upk_sum(ar1);
        float ph = upk_sum(ah0) + upk_sum(ah1);

        if (kh) {
            float4 v; v.x = pz; v.y = pr; v.z = ph; v.w = 0.f;
            *(float4*)&Red[((kh-1)*128 + tl)*4] = v;
        }
        __syncthreads();

        if (!kh) {
            float4 v1 = *(const float4*)&Red[(        tl)*4];
            float4 v2 = *(const float4*)&Red[(128  + tl)*4];
            float4 v3 = *(const float4*)&Red[(256  + tl)*4];
            float hz = pz + v1.x + v2.x + v3.x + bz;
            float hr = pr + v1.y + v2.y + v3.y + br;
            float hh = ph + v1.z + v2.z + v3.z + bh;
            float z    = fast_sigmoid(xz + hz);
            float r    = fast_sigmoid(xr + hr);
            float cand = fast_tanh(xh + r * hh);
            hn = fmaf(z, hn - cand, cand);      // z*h + (1-z)*cand

            // push to next-parity h buffer of every rank (incl. self)
            uint32_t off = off_self + (uint32_t)((p ^ 1) * BGR * KP * 4);
#pragma unroll
            for (int rr = 0; rr < CL; rr++) st_cluster_f32(peerH[rr] + off, hn);
        }

        __syncthreads();                 // all pushes issued CTA-wide
        if (tid < CL) mbar_arrive_cluster(peerM[tid]);

        // latency cover between arrive and wait: y store + next-x prefetch
        if (!kh) {
            y[((size_t)bglob*T_ + tt)*YCH + dir*256 + jglob] = hn;
            if (s + 1 < T_) {
                int tn = dir ? (T_-2-s) : (s+1);
                size_t xrow = ((size_t)bglob*T_ + tn) * X3;
                xz = __ldg(&xp[xrow +       jglob]);
                xr = __ldg(&xp[xrow + 256 + jglob]);
                xh = __ldg(&xp[xrow + 512 + jglob]);
            }
        }

        mbar_wait_parity(mbar, (uint32_t)(s & 1));
        p ^= 1;
    }

    if (kh == 0) {
        if (layer == 2)
            hcat[(size_t)bglob*YCH + dir*256 + jglob] = hn;
        else
            g_h[dir][bglob][jglob] = hn;
    }
    CLUSTER_ARRIVE_();   // keep smem alive until all peers' final pushes land
    CLUSTER_WAIT_();
}

// ---------------------------------------------------------------------------
// launch
// ---------------------------------------------------------------------------
extern "C" void kernel_launch(void* const* d_in, const int* in_sizes, int n_in,
                              void* d_out, int out_size)
{
    (void)in_sizes; (void)n_in; (void)out_size;
    const float* x = (const float*)d_in[0];
    const float* p[18];
    for (int i = 0; i < 18; i++) p[i] = (const float*)d_in[1 + i];
    // layer l: fwk=p[6l], fwr=p[6l+1], fwb=p[6l+2], bwk=p[6l+3], bwr=p[6l+4], bwb=p[6l+5]

    float* y    = (float*)d_out;                    // [B][T][512], inter-layer reuse
    float* hcat = y + (size_t)B_ * T_ * YCH;        // [B][512] final states

    cudaFuncSetAttribute(rec_kernel,
                         cudaFuncAttributeMaxDynamicSharedMemorySize,
                         REC_SMEM_BYTES);
    cudaFuncSetAttribute(gemm_xp_mma_kernel,
                         cudaFuncAttributeMaxDynamicSharedMemorySize,
                         GEMM_SMEM_BYTES);

    const int tot4 = B_*T_*X3/4;
    layer0_xp_kernel<<<(tot4 + 255)/256, 256>>>(x, p[0], p[2], p[3], p[5]);
    rec_kernel<<<128, REC_THREADS, REC_SMEM_BYTES>>>(p[1], p[2], p[4], p[5], y, hcat, 0);

    dim3 gg(X3/128, (B_*T_)/128, 2);
    gemm_xp_mma_kernel<<<gg, 256, GEMM_SMEM_BYTES>>>(y, p[6], p[8], p[9], p[11]);
    rec_kernel<<<128, REC_THREADS, REC_SMEM_BYTES>>>(p[7], p[8], p[10], p[11], y, hcat, 1);

    gemm_xp_mma_kernel<<<gg, 256, GEMM_SMEM_BYTES>>>(y, p[12], p[14], p[15], p[17]);
    rec_kernel<<<128, REC_THREADS, REC_SMEM_BYTES>>>(p[13], p[14], p[16], p[17], y, hcat, 2);
}

// round 14
// speedup vs baseline: 2.3597x; 1.0775x over previous
#include <cuda_runtime.h>
#include <cuda_bf16.h>
#include <cstdint>
#include <math.h>

#define U_  256
#define B_  32
#define T_  2048
#define X3  768      // 3U
#define YCH 512      // 2U
#define KP  260      // padded k-stride (R10 proven)
#define CL  4        // cluster size (ranks)
#define CPR 64       // columns per rank
#define BGR 2        // batch rows per cluster
#define REC_THREADS 512
// smem floats: mbar pad(4) + W(192*KP) + H(2*BGR*KP) + Red(3*128*4)
#define SM_W    4
#define SM_H    (SM_W + 192*KP)
#define SM_RED  (SM_H + 2*BGR*KP)
#define REC_SMEM_FLOATS (SM_RED + 3*128*4)
#define REC_SMEM_BYTES  (REC_SMEM_FLOATS*4)

// GEMM dynamic smem: 4 arrays x 2 stages x 128x40 halves
#define G_STG   5120                    // halves per array-stage
#define GEMM_SMEM_BYTES (8*G_STG*2)     // 81920 B

// Scratch: input projections per direction + inter-layer hidden states
__device__ float g_xp[2][B_*T_*X3];   // [dir][(b*T+t)*768 + c]
__device__ float g_h[2][B_][U_];      // final hidden state handoff between layers

// ---------------------------------------------------------------------------
// helpers
// ---------------------------------------------------------------------------
__device__ __forceinline__ uint32_t smem_u32(const void* p) {
    uint32_t a;
    asm("{ .reg .u64 t; cvta.to.shared.u64 t, %1; cvt.u32.u64 %0, t; }"
        : "=r"(a) : "l"(p));
    return a;
}
__device__ __forceinline__ uint32_t mapa_rank(uint32_t addr, int r) {
    uint32_t out;
    asm("mapa.shared::cluster.u32 %0, %1, %2;" : "=r"(out) : "r"(addr), "r"(r));
    return out;
}
__device__ __forceinline__ void st_cluster_f32(uint32_t addr, float v) {
    asm volatile("st.shared::cluster.f32 [%0], %1;" :: "r"(addr), "f"(v));
}
__device__ __forceinline__ uint32_t ctarank() {
    uint32_t r; asm("mov.u32 %0, %%cluster_ctarank;" : "=r"(r)); return r;
}
#define CLUSTER_ARRIVE_() asm volatile("barrier.cluster.arrive.aligned;" ::: "memory")
#define CLUSTER_WAIT_()   asm volatile("barrier.cluster.wait.aligned;"   ::: "memory")

__device__ __forceinline__ void mbar_init(uint32_t addr, uint32_t cnt) {
    asm volatile("mbarrier.init.shared.b64 [%0], %1;" :: "r"(addr), "r"(cnt) : "memory");
}
__device__ __forceinline__ void mbar_arrive_cluster(uint32_t addr) {
    asm volatile("mbarrier.arrive.release.cluster.shared::cluster.b64 _, [%0];"
                 :: "r"(addr) : "memory");
}
__device__ __forceinline__ void mbar_wait_parity(uint32_t addr, uint32_t parity) {
    asm volatile(
        "{\n\t"
        ".reg .pred P;\n\t"
        "WL%=:\n\t"
        "mbarrier.try_wait.parity.acquire.cluster.shared::cta.b64 P, [%0], %1, 0x989680;\n\t"
        "@!P bra WL%=;\n\t"
        "}"
        :: "r"(addr), "r"(parity) : "memory");
}

__device__ __forceinline__ float fast_sigmoid(float x) {
    return __fdividef(1.f, 1.f + __expf(-x));
}
__device__ __forceinline__ float fast_tanh(float x) {
    float e = __expf(-2.f * x);
    return __fdividef(1.f - e, 1.f + e);
}

// Packed dual fp32 FMA (Blackwell family, PTX ISA 8.6, sm_100+)
__device__ __forceinline__ void ffma2(unsigned long long& d,
                                      unsigned long long a,
                                      unsigned long long b) {
    asm("fma.rn.f32x2 %0, %1, %2, %0;" : "+l"(d) : "l"(a), "l"(b));
}
__device__ __forceinline__ float upk_sum(unsigned long long v) {
    float lo, hi;
    asm("mov.b64 {%0, %1}, %2;" : "=f"(lo), "=f"(hi) : "l"(v));
    return lo + hi;
}

// bf16 HMMA m16n8k16, fp32 accumulate (baseline PTX, legal on sm_100)
__device__ __forceinline__ void mma16816(float* c,
    uint32_t a0, uint32_t a1, uint32_t a2, uint32_t a3,
    uint32_t b0, uint32_t b1)
{
    asm volatile(
        "mma.sync.aligned.m16n8k16.row.col.f32.bf16.bf16.f32 "
        "{%0,%1,%2,%3}, {%4,%5,%6,%7}, {%8,%9}, {%0,%1,%2,%3};"
        : "+f"(c[0]), "+f"(c[1]), "+f"(c[2]), "+f"(c[3])
        : "r"(a0), "r"(a1), "r"(a2), "r"(a3), "r"(b0), "r"(b1));
}

// split one fp32 pair into hi/lo bf16x2 (hi = rn(v), lo = rn(v - hi))
__device__ __forceinline__ void split_pair(float x, float y,
                                           __nv_bfloat162& hi2,
                                           __nv_bfloat162& lo2)
{
    hi2 = __floats2bfloat162_rn(x, y);
    float lx = x - __bfloat162float(__low2bfloat16(hi2));
    float ly = y - __bfloat162float(__high2bfloat16(hi2));
    lo2 = __floats2bfloat162_rn(lx, ly);
}

// ---------------------------------------------------------------------------
// Layer 0 input projection: xp = x * Wk[0,:] + b[0,:]  (in_dim = 1)
// ---------------------------------------------------------------------------
__global__ void layer0_xp_kernel(const float* __restrict__ x,
                                 const float* __restrict__ fwk,
                                 const float* __restrict__ fwb,
                                 const float* __restrict__ bwk,
                                 const float* __restrict__ bwb)
{
    int i4 = blockIdx.x * blockDim.x + threadIdx.x;
    const int tot4 = B_*T_*X3/4;
    if (i4 >= tot4) return;
    int e  = i4 * 4;
    int c  = e % X3;
    int bt = e / X3;
    float xv = __ldg(&x[bt]);
    float4 kf = *(const float4*)&fwk[c];
    float4 bf = *(const float4*)&fwb[c];
    float4 kb = *(const float4*)&bwk[c];
    float4 bb = *(const float4*)&bwb[c];
    float4 of, ob;
    of.x = xv*kf.x + bf.x; of.y = xv*kf.y + bf.y;
    of.z = xv*kf.z + bf.z; of.w = xv*kf.w + bf.w;
    ob.x = xv*kb.x + bb.x; ob.y = xv*kb.y + bb.y;
    ob.z = xv*kb.z + bb.z; ob.w = xv*kb.w + bb.w;
    *(float4*)&g_xp[0][e] = of;
    *(float4*)&g_xp[1][e] = ob;
}

// ---------------------------------------------------------------------------
// Layers 1/2 input projection via bf16-split HMMA GEMM. (R13 proven)
// ---------------------------------------------------------------------------
__global__ void __launch_bounds__(256) gemm_xp_mma_kernel(
    const float* __restrict__ Yin,
    const float* __restrict__ kfw, const float* __restrict__ bfw,
    const float* __restrict__ kbw, const float* __restrict__ bbw)
{
    extern __shared__ __nv_bfloat16 gsm[];

    int dir = blockIdx.z;
    const float* Wk   = dir ? kbw : kfw;
    const float* bias = dir ? bbw : bfw;   // row 0 = input bias
    float* out = g_xp[dir];

    int n0 = blockIdx.x * 128;
    int m0 = blockIdx.y * 128;

    int tid  = threadIdx.x;
    int lane = tid & 31, wid = tid >> 5;
    int wm = wid >> 2, wn = wid & 3;
    int gr = lane >> 2, tc = (lane & 3) * 2;

    int a_row0 = tid >> 4;
    int a_k2   = (tid & 15) * 2;
    int b_n  = tid & 127;
    int b_kp = (tid >> 7) * 2;

    float2 ra[8];
    float  rb0[8], rb1[8];

    float acc[4][4][4];
#pragma unroll
    for (int i = 0; i < 4; i++)
#pragma unroll
        for (int j = 0; j < 4; j++)
#pragma unroll
            for (int q = 0; q < 4; q++) acc[i][j][q] = 0.f;

    // ---- stage kt=0 ----
    {
#pragma unroll
        for (int j = 0; j < 8; j++)
            ra[j] = *(const float2*)&Yin[(size_t)(m0 + a_row0 + 16*j)*YCH + a_k2];
#pragma unroll
        for (int j = 0; j < 8; j++) {
            int k = b_kp + 4*j;
            rb0[j] = __ldg(&Wk[(size_t)k*X3 + n0 + b_n]);
            rb1[j] = __ldg(&Wk[(size_t)(k+1)*X3 + n0 + b_n]);
        }
        __nv_bfloat16* pAh = gsm;
        __nv_bfloat16* pAl = gsm + 2*G_STG;
        __nv_bfloat16* pBh = gsm + 4*G_STG;
        __nv_bfloat16* pBl = gsm + 6*G_STG;
#pragma unroll
        for (int j = 0; j < 8; j++) {
            __nv_bfloat162 h2, l2;
            split_pair(ra[j].x, ra[j].y, h2, l2);
            int off = (a_row0 + 16*j)*40 + a_k2;
            *(__nv_bfloat162*)&pAh[off] = h2;
            *(__nv_bfloat162*)&pAl[off] = l2;
        }
#pragma unroll
        for (int j = 0; j < 8; j++) {
            __nv_bfloat162 h2, l2;
            split_pair(rb0[j], rb1[j], h2, l2);
            int off = b_n*40 + b_kp + 4*j;
            *(__nv_bfloat162*)&pBh[off] = h2;
            *(__nv_bfloat162*)&pBl[off] = l2;
        }
    }
    __syncthreads();

    for (int kt = 0; kt < 16; kt++) {
        int cur = kt & 1;
        if (kt < 15) {
            int kc = (kt + 1) * 32;
#pragma unroll
            for (int j = 0; j < 8; j++)
                ra[j] = *(const float2*)&Yin[(size_t)(m0 + a_row0 + 16*j)*YCH + kc + a_k2];
#pragma unroll
            for (int j = 0; j < 8; j++) {
                int k = kc + b_kp + 4*j;
                rb0[j] = __ldg(&Wk[(size_t)k*X3 + n0 + b_n]);
                rb1[j] = __ldg(&Wk[(size_t)(k+1)*X3 + n0 + b_n]);
            }
        }

        const __nv_bfloat16* pAh = gsm +            cur*G_STG;
        const __nv_bfloat16* pAl = gsm + 2*G_STG +  cur*G_STG;
        const __nv_bfloat16* pBh = gsm + 4*G_STG +  cur*G_STG;
        const __nv_bfloat16* pBl = gsm + 6*G_STG +  cur*G_STG;

#pragma unroll
        for (int kk = 0; kk < 32; kk += 16) {
            uint32_t fbh[4][2], fbl[4][2];
#pragma unroll
            for (int nf = 0; nf < 4; nf++) {
                int n = wn*32 + nf*8 + gr;
                fbh[nf][0] = *(const uint32_t*)&pBh[n*40 + kk + tc];
                fbh[nf][1] = *(const uint32_t*)&pBh[n*40 + kk + tc + 8];
                fbl[nf][0] = *(const uint32_t*)&pBl[n*40 + kk + tc];
                fbl[nf][1] = *(const uint32_t*)&pBl[n*40 + kk + tc + 8];
            }
            uint32_t fah[4][4], fal[4][4];
#pragma unroll
            for (int mf = 0; mf < 4; mf++) {
                int r = wm*64 + mf*16 + gr;
                fah[mf][0] = *(const uint32_t*)&pAh[(r    )*40 + kk + tc];
                fah[mf][1] = *(const uint32_t*)&pAh[(r + 8)*40 + kk + tc];
                fah[mf][2] = *(const uint32_t*)&pAh[(r    )*40 + kk + tc + 8];
                fah[mf][3] = *(const uint32_t*)&pAh[(r + 8)*40 + kk + tc + 8];
                fal[mf][0] = *(const uint32_t*)&pAl[(r    )*40 + kk + tc];
                fal[mf][1] = *(const uint32_t*)&pAl[(r + 8)*40 + kk + tc];
                fal[mf][2] = *(const uint32_t*)&pAl[(r    )*40 + kk + tc + 8];
                fal[mf][3] = *(const uint32_t*)&pAl[(r + 8)*40 + kk + tc + 8];
            }
#pragma unroll
            for (int mf = 0; mf < 4; mf++)
#pragma unroll
                for (int nf = 0; nf < 4; nf++)
                    mma16816(acc[mf][nf], fah[mf][0], fah[mf][1], fah[mf][2],
                             fah[mf][3], fbh[nf][0], fbh[nf][1]);
#pragma unroll
            for (int mf = 0; mf < 4; mf++)
#pragma unroll
                for (int nf = 0; nf < 4; nf++)
                    mma16816(acc[mf][nf], fal[mf][0], fal[mf][1], fal[mf][2],
                             fal[mf][3], fbh[nf][0], fbh[nf][1]);
#pragma unroll
            for (int mf = 0; mf < 4; mf++)
#pragma unroll
                for (int nf = 0; nf < 4; nf++)
                    mma16816(acc[mf][nf], fah[mf][0], fah[mf][1], fah[mf][2],
                             fah[mf][3], fbl[nf][0], fbl[nf][1]);
        }

        if (kt < 15) {
            int nxt = cur ^ 1;
            __nv_bfloat16* qAh = gsm +            nxt*G_STG;
            __nv_bfloat16* qAl = gsm + 2*G_STG +  nxt*G_STG;
            __nv_bfloat16* qBh = gsm + 4*G_STG +  nxt*G_STG;
            __nv_bfloat16* qBl = gsm + 6*G_STG +  nxt*G_STG;
#pragma unroll
            for (int j = 0; j < 8; j++) {
                __nv_bfloat162 h2, l2;
                split_pair(ra[j].x, ra[j].y, h2, l2);
                int off = (a_row0 + 16*j)*40 + a_k2;
                *(__nv_bfloat162*)&qAh[off] = h2;
                *(__nv_bfloat162*)&qAl[off] = l2;
            }
#pragma unroll
            for (int j = 0; j < 8; j++) {
                __nv_bfloat162 h2, l2;
                split_pair(rb0[j], rb1[j], h2, l2);
                int off = b_n*40 + b_kp + 4*j;
                *(__nv_bfloat162*)&qBh[off] = h2;
                *(__nv_bfloat162*)&qBl[off] = l2;
            }
        }
        __syncthreads();
    }

    // Epilogue
#pragma unroll
    for (int mf = 0; mf < 4; mf++) {
        int row = m0 + wm*64 + mf*16 + gr;
#pragma unroll
        for (int nf = 0; nf < 4; nf++) {
            int col = n0 + wn*32 + nf*8 + tc;
            float b0 = __ldg(&bias[col]), b1 = __ldg(&bias[col + 1]);
            float2 lo, hi;
            lo.x = acc[mf][nf][0] + b0; lo.y = acc[mf][nf][1] + b1;
            hi.x = acc[mf][nf][2] + b0; hi.y = acc[mf][nf][3] + b1;
            *(float2*)&out[(size_t)row * X3 + col]       = lo;
            *(float2*)&out[(size_t)(row + 8) * X3 + col] = hi;
        }
    }
}

// ---------------------------------------------------------------------------
// Recurrence. Grid = 128 CTAs, clusters of 4, 512 threads.
//   R14: self-chunk pre-dot. k-range per thread is 4 chunks of 16 cols;
//   chunk 0 = this rank's own columns (written locally, valid after bar2).
//   After bar2/arrive, every thread computes the NEXT step's dot over its
//   self chunk, overlapping the remote-arrive latency; the remaining 3
//   chunks run after the parity wait. Protocol otherwise identical to R10.
// ---------------------------------------------------------------------------
__global__ void __cluster_dims__(CL, 1, 1) __launch_bounds__(REC_THREADS, 1)
rec_kernel(const float* __restrict__ wr_fw, const float* __restrict__ bias_fw,
           const float* __restrict__ wr_bw, const float* __restrict__ bias_bw,
           float* __restrict__ y, float* __restrict__ hcat, int layer)
{
    extern __shared__ float sm[];
    float* Wsm = sm + SM_W;          // [192][KP]
    float* Hsm = sm + SM_H;          // [2][BGR][KP]
    float* Red = sm + SM_RED;        // [3][128][4]
    uint32_t mbar = smem_u32(sm);    // 8B mbarrier at sm[0..1]

    int rank = (int)ctarank();
    int cidx = blockIdx.x >> 2;       // 0..31
    int dir  = cidx >> 4;             // 0 fw, 1 bw
    int bg   = cidx & 15;             // batch group (2 rows)
    int tid  = threadIdx.x;
    int kh   = tid >> 7;              // k-quarter 0..3
    int tl   = tid & 127;
    int jl   = tl >> 1;               // 0..63 local column
    int bl   = tl & 1;                // 0..1 local batch
    int jglob = rank*CPR + jl;
    int bglob = bg*BGR + bl;

    const float* Wr   = dir ? wr_bw   : wr_fw;
    const float* bias = dir ? bias_bw : bias_fw;
    const float* xp   = g_xp[dir];

    if (tid == 0) mbar_init(mbar, CL);

    // Load weight slice: Wsm[(g*64+j)*KP + k] = Wr[k][g*256 + rank*64 + j]
    for (int idx = tid; idx < 192*256; idx += REC_THREADS) {
        int k    = idx / 192;
        int r192 = idx - k*192;
        int g = r192 >> 6, j = r192 & 63;
        Wsm[(g*CPR + j)*KP + k] = __ldg(&Wr[k*X3 + g*256 + rank*CPR + j]);
    }
    // Initial hidden state into parity-0 buffer
    for (int i = tid; i < BGR*256; i += REC_THREADS) {
        int b = i >> 8, k = i & 255;
        Hsm[b*KP + k] = layer ? g_h[dir][bg*BGR + b][k] : 0.f;
    }
    // Recurrent biases (row 1 of bias array) — only needed by kh=0
    float bz = 0.f, br = 0.f, bh = 0.f;
    if (kh == 0) {
        bz = __ldg(&bias[X3 +       jglob]);
        br = __ldg(&bias[X3 + 256 + jglob]);
        bh = __ldg(&bias[X3 + 512 + jglob]);
    }
    __syncthreads();
    CLUSTER_ARRIVE_();   // all mbarriers initialised + H/W loaded cluster-wide
    CLUSTER_WAIT_();

    uint32_t hbase = smem_u32(Hsm);
    uint32_t peerH[CL], peerM[CL];
#pragma unroll
    for (int r = 0; r < CL; r++) {
        peerH[r] = mapa_rank(hbase, r);
        peerM[r] = mapa_rank(mbar, r);
    }
    uint32_t off_self = (uint32_t)((bl*KP + jglob) * 4);

    // chunk table: chunk c covers ulonglong2 indices [4c, 4c+4); c0 = self
    int cb0 = ((rank*4 + kh     ) & 15) * 4;
    int cb1 = ((rank*4 + kh + 4 ) & 15) * 4;
    int cb2 = ((rank*4 + kh + 8 ) & 15) * 4;
    int cb3 = ((rank*4 + kh + 12) & 15) * 4;

    const ulonglong2* wz2 = (const ulonglong2*)(Wsm + (          jl)*KP);
    const ulonglong2* wr2 = (const ulonglong2*)(Wsm + ( CPR    + jl)*KP);
    const ulonglong2* wh2 = (const ulonglong2*)(Wsm + (2*CPR   + jl)*KP);

    // h(t-1) for this (jglob,bl) carried in-register by kh==0 threads
    float hn = (kh == 0) ? Hsm[bl*KP + jglob] : 0.f;

    // prefetch xp for step 0
    float xz = 0.f, xr = 0.f, xh = 0.f;
    if (kh == 0) {
        int tt0 = dir ? (T_-1) : 0;
        size_t xrow = ((size_t)bglob*T_ + tt0) * X3;
        xz = __ldg(&xp[xrow +       jglob]);
        xr = __ldg(&xp[xrow + 256 + jglob]);
        xh = __ldg(&xp[xrow + 512 + jglob]);
    }

    unsigned long long az0 = 0ull, az1 = 0ull;
    unsigned long long ar0 = 0ull, ar1 = 0ull;
    unsigned long long ah0 = 0ull, ah1 = 0ull;

    // initial pre-dot: self chunk of H[p=0] (ready after cluster sync)
    {
        const ulonglong2* hv2 = (const ulonglong2*)(Hsm + bl*KP);
#pragma unroll
        for (int j = 0; j < 4; j++) {
            int idx = cb0 + j;
            ulonglong2 h2 = hv2[idx];
            ulonglong2 w;
            w = wz2[idx]; ffma2(az0, w.x, h2.x); ffma2(az1, w.y, h2.y);
            w = wr2[idx]; ffma2(ar0, w.x, h2.x); ffma2(ar1, w.y, h2.y);
            w = wh2[idx]; ffma2(ah0, w.x, h2.x); ffma2(ah1, w.y, h2.y);
        }
    }

    int p = 0;
    for (int s = 0; s < T_; s++) {
        int tt = dir ? (T_-1-s) : s;

        // main dot: the 3 remote chunks of H[p]
        const ulonglong2* hv2 = (const ulonglong2*)(Hsm + (p*BGR + bl)*KP);
#pragma unroll
        for (int j = 0; j < 4; j++) {
            int idx = cb1 + j;
            ulonglong2 h2 = hv2[idx];
            ulonglong2 w;
            w = wz2[idx]; ffma2(az0, w.x, h2.x); ffma2(az1, w.y, h2.y);
            w = wr2[idx]; ffma2(ar0, w.x, h2.x); ffma2(ar1, w.y, h2.y);
            w = wh2[idx]; ffma2(ah0, w.x, h2.x); ffma2(ah1, w.y, h2.y);
        }
#pragma unroll
        for (int j = 0; j < 4; j++) {
            int idx = cb2 + j;
            ulonglong2 h2 = hv2[idx];
            ulonglong2 w;
            w = wz2[idx]; ffma2(az0, w.x, h2.x); ffma2(az1, w.y, h2.y);
            w = wr2[idx]; ffma2(ar0, w.x, h2.x); ffma2(ar1, w.y, h2.y);
            w = wh2[idx]; ffma2(ah0, w.x, h2.x); ffma2(ah1, w.y, h2.y);
        }
#pragma unroll
        for (int j = 0; j < 4; j++) {
            int idx = cb3 + j;
            ulonglong2 h2 = hv2[idx];
            ulonglong2 w;
            w = wz2[idx]; ffma2(az0, w.x, h2.x); ffma2(az1, w.y, h2.y);
            w = wr2[idx]; ffma2(ar0, w.x, h2.x); ffma2(ar1, w.y, h2.y);
            w = wh2[idx]; ffma2(ah0, w.x, h2.x); ffma2(ah1, w.y, h2.y);
        }
        float pz = upk_sum(az0) + upk_sum(az1);
        float pr = upk_sum(ar0) + upk_sum(ar1);
        float ph = upk_sum(ah0) + upk_sum(ah1);
        az0 = az1 = ar0 = ar1 = ah0 = ah1 = 0ull;

        if (kh) {
            float4 v; v.x = pz; v.y = pr; v.z = ph; v.w = 0.f;
            *(float4*)&Red[((kh-1)*128 + tl)*4] = v;
        }
        __syncthreads();

        if (!kh) {
            float4 v1 = *(const float4*)&Red[(        tl)*4];
            float4 v2 = *(const float4*)&Red[(128  + tl)*4];
            float4 v3 = *(const float4*)&Red[(256  + tl)*4];
            float hz = pz + v1.x + v2.x + v3.x + bz;
            float hr = pr + v1.y + v2.y + v3.y + br;
            float hh = ph + v1.z + v2.z + v3.z + bh;
            float z    = fast_sigmoid(xz + hz);
            float r    = fast_sigmoid(xr + hr);
            float cand = fast_tanh(xh + r * hh);
            hn = fmaf(z, hn - cand, cand);      // z*h + (1-z)*cand

            // push to next-parity h buffer of every rank (incl. self)
            uint32_t off = off_self + (uint32_t)((p ^ 1) * BGR * KP * 4);
#pragma unroll
            for (int rr = 0; rr < CL; rr++) st_cluster_f32(peerH[rr] + off, hn);
        }

        __syncthreads();                 // all pushes issued CTA-wide
        if (tid < CL) mbar_arrive_cluster(peerM[tid]);

        // latency cover: y store + next-x prefetch (gate warps)
        if (!kh) {
            y[((size_t)bglob*T_ + tt)*YCH + dir*256 + jglob] = hn;
            if (s + 1 < T_) {
                int tn = dir ? (T_-2-s) : (s+1);
                size_t xrow = ((size_t)bglob*T_ + tn) * X3;
                xz = __ldg(&xp[xrow +       jglob]);
                xr = __ldg(&xp[xrow + 256 + jglob]);
                xh = __ldg(&xp[xrow + 512 + jglob]);
            }
        }

        // pre-dot for next step: self chunk of H[p^1] — written by LOCAL
        // gate warps, ordered by the __syncthreads above (no acquire needed).
        {
            const ulonglong2* hn2 =
                (const ulonglong2*)(Hsm + ((p ^ 1)*BGR + bl)*KP);
#pragma unroll
            for (int j = 0; j < 4; j++) {
                int idx = cb0 + j;
                ulonglong2 h2 = hn2[idx];
                ulonglong2 w;
                w = wz2[idx]; ffma2(az0, w.x, h2.x); ffma2(az1, w.y, h2.y);
                w = wr2[idx]; ffma2(ar0, w.x, h2.x); ffma2(ar1, w.y, h2.y);
                w = wh2[idx]; ffma2(ah0, w.x, h2.x); ffma2(ah1, w.y, h2.y);
            }
        }

        mbar_wait_parity(mbar, (uint32_t)(s & 1));
        p ^= 1;
    }

    if (kh == 0) {
        if (layer == 2)
            hcat[(size_t)bglob*YCH + dir*256 + jglob] = hn;
        else
            g_h[dir][bglob][jglob] = hn;
    }
    CLUSTER_ARRIVE_();   // keep smem alive until all peers' final pushes land
    CLUSTER_WAIT_();
}

// ---------------------------------------------------------------------------
// launch
// ---------------------------------------------------------------------------
extern "C" void kernel_launch(void* const* d_in, const int* in_sizes, int n_in,
                              void* d_out, int out_size)
{
    (void)in_sizes; (void)n_in; (void)out_size;
    const float* x = (const float*)d_in[0];
    const float* p[18];
    for (int i = 0; i < 18; i++) p[i] = (const float*)d_in[1 + i];
    // layer l: fwk=p[6l], fwr=p[6l+1], fwb=p[6l+2], bwk=p[6l+3], bwr=p[6l+4], bwb=p[6l+5]

    float* y    = (float*)d_out;                    // [B][T][512], inter-layer reuse
    float* hcat = y + (size_t)B_ * T_ * YCH;        // [B][512] final states

    cudaFuncSetAttribute(rec_kernel,
                         cudaFuncAttributeMaxDynamicSharedMemorySize,
                         REC_SMEM_BYTES);
    cudaFuncSetAttribute(gemm_xp_mma_kernel,
                         cudaFuncAttributeMaxDynamicSharedMemorySize,
                         GEMM_SMEM_BYTES);

    const int tot4 = B_*T_*X3/4;
    layer0_xp_kernel<<<(tot4 + 255)/256, 256>>>(x, p[0], p[2], p[3], p[5]);
    rec_kernel<<<128, REC_THREADS, REC_SMEM_BYTES>>>(p[1], p[2], p[4], p[5], y, hcat, 0);

    dim3 gg(X3/128, (B_*T_)/128, 2);
    gemm_xp_mma_kernel<<<gg, 256, GEMM_SMEM_BYTES>>>(y, p[6], p[8], p[9], p[11]);
    rec_kernel<<<128, REC_THREADS, REC_SMEM_BYTES>>>(p[7], p[8], p[10], p[11], y, hcat, 1);

    gemm_xp_mma_kernel<<<gg, 256, GEMM_SMEM_BYTES>>>(y, p[12], p[14], p[15], p[17]);
    rec_kernel<<<128, REC_THREADS, REC_SMEM_BYTES>>>(p[13], p[14], p[16], p[17], y, hcat, 2);
}